// round 14
// baseline (speedup 1.0000x reference)
#include <cuda_runtime.h>
#include <cuda_bf16.h>
#include <math.h>
#include <stdint.h>

#define BATCH 128
#define SEQ   512
#define NDIM  1024
#define RGRID 128          // persistent CTAs: 4 m-groups x 32 n-blocks

// ---------------------------------------------------------------------------
// Global scratch (allocation-free)
// ---------------------------------------------------------------------------
__device__ float g_xp[(size_t)BATCH * SEQ * NDIM];        // 256 MB
__device__ __nv_bfloat16 g_Wt_hi[(size_t)NDIM * NDIM];    // W_xh^T hi  [N][K]
__device__ __nv_bfloat16 g_Wt_lo[(size_t)NDIM * NDIM];
__device__ __nv_bfloat16 g_Whh_hi[(size_t)NDIM * NDIM];   // W_hh^T hi  [N][K]
__device__ __nv_bfloat16 g_Whh_lo[(size_t)NDIM * NDIM];
__device__ __nv_bfloat16 g_hbf_hi[2][BATCH * NDIM];       // ping-pong h hi
__device__ __nv_bfloat16 g_hbf_lo[2][BATCH * NDIM];       // ping-pong h lo
__device__ float g_hfin[BATCH * NDIM];                    // final h fp32
__device__ unsigned g_gcnt[4 * 32];                       // init-barrier counters
__device__ unsigned g_ggen[4 * 32];                       // init-barrier generations
__device__ __align__(128) unsigned g_sflag[4][32];        // per-CTA step flags (1 line/group)

// ---------------------------------------------------------------------------
// Helpers
// ---------------------------------------------------------------------------
__device__ __forceinline__ uint32_t smem_u32(const void* p) {
    uint32_t a;
    asm("{ .reg .u64 t; cvta.to.shared.u64 t, %1; cvt.u32.u64 %0, t; }"
        : "=r"(a) : "l"(p));
    return a;
}

__device__ __forceinline__ void ldsm4(uint32_t (&r)[4], uint32_t addr) {
    asm volatile("ldmatrix.sync.aligned.m8n8.x4.shared.b16 {%0,%1,%2,%3}, [%4];"
                 : "=r"(r[0]), "=r"(r[1]), "=r"(r[2]), "=r"(r[3]) : "r"(addr));
}

__device__ __forceinline__ void mma_bf16(float (&d)[4], const uint32_t (&a)[4],
                                         const uint32_t b0, const uint32_t b1) {
    asm volatile(
        "mma.sync.aligned.m16n8k16.row.col.f32.bf16.bf16.f32 "
        "{%0,%1,%2,%3}, {%4,%5,%6,%7}, {%8,%9}, {%0,%1,%2,%3};"
        : "+f"(d[0]), "+f"(d[1]), "+f"(d[2]), "+f"(d[3])
        : "r"(a[0]), "r"(a[1]), "r"(a[2]), "r"(a[3]), "r"(b0), "r"(b1));
}

#define CP_ASYNC16(dst, src) \
    asm volatile("cp.async.cg.shared.global [%0], [%1], 16;" \
                 :: "r"(dst), "l"(src) : "memory")
#define CP_COMMIT() asm volatile("cp.async.commit_group;" ::: "memory")
#define CP_WAIT0()  asm volatile("cp.async.wait_group 0;" ::: "memory")
#define BAR_PAIR(id) asm volatile("bar.sync %0, 64;" :: "r"(id) : "memory")
#define BAR_GRP(id)  asm volatile("bar.sync %0, 128;" :: "r"(id) : "memory")

// split 8 fp32 -> 8 bf16 hi + 8 bf16 lo (packed uint4 each)
__device__ __forceinline__ void split8(float4 f0, float4 f1, uint4& hi, uint4& lo) {
    float f[8] = {f0.x, f0.y, f0.z, f0.w, f1.x, f1.y, f1.z, f1.w};
    unsigned short h[8], l[8];
#pragma unroll
    for (int i = 0; i < 8; i++) {
        __nv_bfloat16 bh = __float2bfloat16_rn(f[i]);
        float r = f[i] - __bfloat162float(bh);
        h[i] = __bfloat16_as_ushort(bh);
        l[i] = __bfloat16_as_ushort(__float2bfloat16_rn(r));
    }
    hi.x = (uint32_t)h[0] | ((uint32_t)h[1] << 16);
    hi.y = (uint32_t)h[2] | ((uint32_t)h[3] << 16);
    hi.z = (uint32_t)h[4] | ((uint32_t)h[5] << 16);
    hi.w = (uint32_t)h[6] | ((uint32_t)h[7] << 16);
    lo.x = (uint32_t)l[0] | ((uint32_t)l[1] << 16);
    lo.y = (uint32_t)l[2] | ((uint32_t)l[3] << 16);
    lo.z = (uint32_t)l[4] | ((uint32_t)l[5] << 16);
    lo.w = (uint32_t)l[6] | ((uint32_t)l[7] << 16);
}

// split 2 fp32 -> packed bf16x2 hi + lo
__device__ __forceinline__ void split2(float a, float b, uint32_t& hi, uint32_t& lo) {
    __nv_bfloat16 ah = __float2bfloat16_rn(a), bh = __float2bfloat16_rn(b);
    float ar = a - __bfloat162float(ah), br = b - __bfloat162float(bh);
    hi = (uint32_t)__bfloat16_as_ushort(ah) |
         ((uint32_t)__bfloat16_as_ushort(bh) << 16);
    lo = (uint32_t)__bfloat16_as_ushort(__float2bfloat16_rn(ar)) |
         ((uint32_t)__bfloat16_as_ushort(__float2bfloat16_rn(br)) << 16);
}

// one-time 32-CTA group barrier (replay-safe, monotonic generation)
__device__ __forceinline__ void group_barrier(int grp) {
    __syncthreads();
    if (threadIdx.x == 0) {
        unsigned* cnt = &g_gcnt[grp * 32];
        volatile unsigned* gen = (volatile unsigned*)&g_ggen[grp * 32];
        unsigned myg = *gen;
        __threadfence();
        if (atomicAdd(cnt, 1) == 31) {
            atomicExch(cnt, 0);
            __threadfence();
            atomicAdd((unsigned*)gen, 1);
        } else {
            while (*gen == myg) { }
            __threadfence();
        }
    }
    __syncthreads();
}

// ---------------------------------------------------------------------------
// Setup kernels
// ---------------------------------------------------------------------------
__global__ void zero_hbf() {
    int idx = blockIdx.x * blockDim.x + threadIdx.x;
    if (idx < BATCH * NDIM) {
        g_hbf_hi[0][idx] = __float2bfloat16_rn(0.0f);
        g_hbf_lo[0][idx] = __float2bfloat16_rn(0.0f);
    }
}

// Transpose + split W [K,N] -> dst_hi/lo [N,K] bf16.  blockIdx.z: 0=W_xh, 1=W_hh
__global__ void wprep(const float* __restrict__ Wxh, const float* __restrict__ Whh) {
    __shared__ float t[32][33];
    const int which = blockIdx.z;
    const float* W = which ? Whh : Wxh;
    __nv_bfloat16* dhi = which ? g_Whh_hi : g_Wt_hi;
    __nv_bfloat16* dlo = which ? g_Whh_lo : g_Wt_lo;
    int tx = threadIdx.x, ty = threadIdx.y;
    int nb = blockIdx.x * 32, kb = blockIdx.y * 32;
#pragma unroll
    for (int i = ty; i < 32; i += 8)
        t[i][tx] = W[(size_t)(kb + i) * NDIM + nb + tx];
    __syncthreads();
#pragma unroll
    for (int i = ty; i < 32; i += 8) {
        float f = t[tx][i];
        __nv_bfloat16 bh = __float2bfloat16_rn(f);
        float r = f - __bfloat162float(bh);
        size_t off = (size_t)(nb + i) * NDIM + kb + tx;
        dhi[off] = bh;
        dlo[off] = __float2bfloat16_rn(r);
    }
}

// ---------------------------------------------------------------------------
// XP GEMM via mma.sync bf16-split (unchanged)
// ---------------------------------------------------------------------------
#define XP_ARR  10240
#define XP_BUF  (4 * XP_ARR)
#define XP_SMEM (2 * XP_BUF)

__global__ void __launch_bounds__(256) xp_gemm_mma(const float* __restrict__ A,
                                                   const float* __restrict__ bias) {
    extern __shared__ __align__(16) unsigned char sm[];
    const uint32_t sb = smem_u32(sm);
    const int tid = threadIdx.x, wid = tid >> 5, lane = tid & 31;
    const int cCol = blockIdx.x, cRow = blockIdx.y;
    const int wm = (wid >> 2) * 64;
    const int wn = (wid & 3) * 32;

    const int lrow = tid >> 1;
    const int lhf  = tid & 1;
    const float* Ag = A + (size_t)(cRow * 128 + lrow) * NDIM + lhf * 16;
    const __nv_bfloat16* Bhg = g_Wt_hi + (size_t)(cCol * 128 + lrow) * NDIM + lhf * 16;
    const __nv_bfloat16* Blg = g_Wt_lo + (size_t)(cCol * 128 + lrow) * NDIM + lhf * 16;
    unsigned char* st_a = sm + lrow * 80 + lhf * 32;
    unsigned char* st_b = sm + 2 * XP_ARR + lrow * 80 + lhf * 32;

    float acc[4][4][4];
#pragma unroll
    for (int i = 0; i < 4; i++)
#pragma unroll
        for (int j = 0; j < 4; j++)
#pragma unroll
            for (int q = 0; q < 4; q++) acc[i][j][q] = 0.0f;

    {
        float4 f0 = *(const float4*)(Ag + 0);
        float4 f1 = *(const float4*)(Ag + 4);
        float4 f2 = *(const float4*)(Ag + 8);
        float4 f3 = *(const float4*)(Ag + 12);
        uint4 h0, l0, h1, l1;
        split8(f0, f1, h0, l0);
        split8(f2, f3, h1, l1);
        *(uint4*)(st_a +  0) = h0; *(uint4*)(st_a + 16) = h1;
        *(uint4*)(st_a + XP_ARR +  0) = l0; *(uint4*)(st_a + XP_ARR + 16) = l1;
        uint4 bh0 = *(const uint4*)(Bhg);     uint4 bh1 = *(const uint4*)(Bhg + 8);
        uint4 bl0 = *(const uint4*)(Blg);     uint4 bl1 = *(const uint4*)(Blg + 8);
        *(uint4*)(st_b +  0) = bh0; *(uint4*)(st_b + 16) = bh1;
        *(uint4*)(st_b + XP_ARR +  0) = bl0; *(uint4*)(st_b + XP_ARR + 16) = bl1;
    }
    __syncthreads();

#pragma unroll 1
    for (int ko = 0; ko < 32; ko++) {
        const int buf = ko & 1;
        float4 f0, f1, f2, f3;
        uint4 pbh0, pbh1, pbl0, pbl1;
        if (ko < 31) {
            const float* Ap = Ag + (ko + 1) * 32;
            f0 = *(const float4*)(Ap + 0);  f1 = *(const float4*)(Ap + 4);
            f2 = *(const float4*)(Ap + 8);  f3 = *(const float4*)(Ap + 12);
            pbh0 = *(const uint4*)(Bhg + (ko + 1) * 32);
            pbh1 = *(const uint4*)(Bhg + (ko + 1) * 32 + 8);
            pbl0 = *(const uint4*)(Blg + (ko + 1) * 32);
            pbl1 = *(const uint4*)(Blg + (ko + 1) * 32 + 8);
        }

        const uint32_t base = sb + buf * XP_BUF;
#pragma unroll
        for (int s = 0; s < 2; s++) {
            const uint32_t k0b = s * 32;
            uint32_t ah[4][4], al[4][4];
#pragma unroll
            for (int mi = 0; mi < 4; mi++) {
                uint32_t ad = base + (wm + mi * 16 + (lane & 15)) * 80 + k0b + (lane >> 4) * 16;
                ldsm4(ah[mi], ad);
                ldsm4(al[mi], ad + XP_ARR);
            }
            uint32_t bh[4][2], bl[4][2];
#pragma unroll
            for (int nb = 0; nb < 2; nb++) {
                uint32_t bd = base + 2 * XP_ARR +
                              (wn + nb * 16 + (lane & 7) + ((lane >> 4) << 3)) * 80 +
                              k0b + (((lane >> 3) & 1) << 4);
                uint32_t r[4];
                ldsm4(r, bd);
                bh[nb * 2 + 0][0] = r[0]; bh[nb * 2 + 0][1] = r[1];
                bh[nb * 2 + 1][0] = r[2]; bh[nb * 2 + 1][1] = r[3];
                ldsm4(r, bd + XP_ARR);
                bl[nb * 2 + 0][0] = r[0]; bl[nb * 2 + 0][1] = r[1];
                bl[nb * 2 + 1][0] = r[2]; bl[nb * 2 + 1][1] = r[3];
            }
#pragma unroll
            for (int mi = 0; mi < 4; mi++)
#pragma unroll
                for (int nj = 0; nj < 4; nj++) {
                    mma_bf16(acc[mi][nj], ah[mi], bh[nj][0], bh[nj][1]);
                    mma_bf16(acc[mi][nj], ah[mi], bl[nj][0], bl[nj][1]);
                    mma_bf16(acc[mi][nj], al[mi], bh[nj][0], bh[nj][1]);
                }
        }

        if (ko < 31) {
            unsigned char* da = st_a + (buf ^ 1) * XP_BUF;
            unsigned char* db = st_b + (buf ^ 1) * XP_BUF;
            uint4 h0, l0, h1, l1;
            split8(f0, f1, h0, l0);
            split8(f2, f3, h1, l1);
            *(uint4*)(da +  0) = h0; *(uint4*)(da + 16) = h1;
            *(uint4*)(da + XP_ARR +  0) = l0; *(uint4*)(da + XP_ARR + 16) = l1;
            *(uint4*)(db +  0) = pbh0; *(uint4*)(db + 16) = pbh1;
            *(uint4*)(db + XP_ARR +  0) = pbl0; *(uint4*)(db + XP_ARR + 16) = pbl1;
            __syncthreads();
        }
    }

#pragma unroll
    for (int mi = 0; mi < 4; mi++) {
        int row = cRow * 128 + wm + mi * 16 + (lane >> 2);
#pragma unroll
        for (int nj = 0; nj < 4; nj++) {
            int col = cCol * 128 + wn + nj * 8 + (lane & 3) * 2;
            float b0 = bias[col], b1 = bias[col + 1];
            float2 v0 = {acc[mi][nj][0] + b0, acc[mi][nj][1] + b1};
            float2 v1 = {acc[mi][nj][2] + b0, acc[mi][nj][3] + b1};
            *(float2*)(g_xp + (size_t)row * NDIM + col) = v0;
            *(float2*)(g_xp + (size_t)(row + 8) * NDIM + col) = v1;
        }
    }
}

// ---------------------------------------------------------------------------
// Persistent recurrence v11: R13 winner (per-pair h staging) + group-local
// combine barriers. Per step there are now ZERO block-wide syncs:
//   pair barriers (64t, ids 1..8) for h staging,
//   combine-group barriers (128t, ids 9..12) for the k-quarter reduction,
//   epilogue barrier (128t, id 15) before publish.
// Cross-step WAR on the red area is ordered by the release/acquire flag
// chain (kq=0 reads -> bar15 -> fence+RED publish; consumers acquire-load).
// ---------------------------------------------------------------------------
#define R4_WS     2064
#define R4_OFFW   0
#define R4_OFFWL  66048
#define R4_OFFH   132096
#define R4_PAIR   9216                 // per pair: 2 bufs x (hi 2304 + lo 2304)
#define R4_BUF    4608
#define R4_HLO    2304
#define R4_OFFRED (132096 + 8 * 9216)  // 205824
#define R4_REDSL  4096
#define R4_SMEM   (205824 + 3 * 4096)  // 218112

__global__ void __launch_bounds__(512) rnn_persistent11() {
    extern __shared__ __align__(16) unsigned char sm[];
    const uint32_t sb = smem_u32(sm);
    const int tid = threadIdx.x, wid = tid >> 5, lane = tid & 31;
    const int r  = blockIdx.x;
    const int mi = r >> 5;          // m-group 0..3
    const int nj = r & 31;          // n-block 0..31
    const int mq = (wid >> 1) & 1;  // quadrant m
    const int nq = wid & 1;         // quadrant n
    const int kq = wid >> 2;        // k-quarter 0..3
    const int pair = wid >> 1;      // 0..7 : (kq, mq) pair shared by nq=0,1
    const int barid = 1 + pair;     // pair barriers: ids 1..8
    const int gbar  = 9 + (mq * 2 + nq);  // combine-group barriers: ids 9..12

    // snapshot my lane's flag base BEFORE anyone publishes (replay-safe)
    const unsigned fbase = *((volatile unsigned*)&g_sflag[mi][lane]);
    const unsigned* fptr = &g_sflag[mi][lane];

    // ---- load W_hh^T rows [nj*32, +32) into smem (once, persistent) ----
    {
        const int n  = tid >> 4;             // 0..31
        const int sg = (tid & 15) * 128;     // byte offset within 2048B row
        const unsigned char* gh = (const unsigned char*)(g_Whh_hi + (size_t)(nj * 32 + n) * NDIM) + sg;
        const unsigned char* gl = (const unsigned char*)(g_Whh_lo + (size_t)(nj * 32 + n) * NDIM) + sg;
        uint32_t dh = sb + R4_OFFW  + n * R4_WS + sg;
        uint32_t dl = sb + R4_OFFWL + n * R4_WS + sg;
#pragma unroll
        for (int i = 0; i < 8; i++) {
            CP_ASYNC16(dh + i * 16, gh + i * 16);
            CP_ASYNC16(dl + i * 16, gl + i * 16);
        }
        CP_COMMIT();
    }

    group_barrier(mi);   // all snapshots taken; safe to start publishing

    // pair-local h loader geometry: 64 threads cover 16 rows x 128B
    const int ptid = nq * 32 + lane;        // 0..63 within pair
    const int prow = ptid >> 2;             // 0..15
    const int pseg = (ptid & 3) * 32;       // 0,32,64,96
    const uint32_t hpair = sb + R4_OFFH + pair * R4_PAIR;
    const uint32_t hdst  = hpair + prow * 144 + pseg;   // +buf*R4_BUF, lo +R4_HLO

    // epilogue geometry (kq==0 warps, wid 0..3)
    const int erow = mi * 32 + mq * 16 + (lane >> 2);
    const int ecol = nj * 32 + nq * 16 + (lane & 3) * 2;

    CP_WAIT0();
    __syncthreads();

#pragma unroll 1
    for (int t = 0; t < SEQ; t++) {
        // per-thread global h source: row mi*32+mq*16+prow, col window kq*128+pseg
        const unsigned char* HgH =
            (const unsigned char*)(g_hbf_hi[t & 1] + (size_t)(mi * 32 + mq * 16 + prow) * NDIM)
            + kq * 128 + pseg;
        const unsigned char* HgL =
            (const unsigned char*)(g_hbf_lo[t & 1] + (size_t)(mi * 32 + mq * 16 + prow) * NDIM)
            + kq * 128 + pseg;

        // xp prefetch (epilogue warps) — before any waiting
        float2 xp00, xp01, xp10, xp11;
        if (kq == 0) {
            const float* b0 = g_xp + ((size_t)erow * SEQ + t) * NDIM;
            const float* b1 = g_xp + ((size_t)(erow + 8) * SEQ + t) * NDIM;
            xp00 = *(const float2*)(b0 + ecol);
            xp01 = *(const float2*)(b0 + ecol + 8);
            xp10 = *(const float2*)(b1 + ecol);
            xp11 = *(const float2*)(b1 + ecol + 8);
        }

        // ---- wait: all 32 producers of h(t) published (acquire-load poll) ----
        if (t > 0) {
            const unsigned target = fbase + (unsigned)t;
            unsigned v;
            do {
                asm volatile("ld.global.acquire.gpu.b32 %0, [%1];"
                             : "=r"(v) : "l"(fptr) : "memory");
            } while (!__all_sync(0xFFFFFFFFu, (int)(v - target) >= 0));
        }

        // prologue: chunk 0 -> buf 0 (pair-local, 64-thread barrier)
        CP_ASYNC16(hdst,                HgH);
        CP_ASYNC16(hdst + 16,           HgH + 16);
        CP_ASYNC16(hdst + R4_HLO,       HgL);
        CP_ASYNC16(hdst + R4_HLO + 16,  HgL + 16);
        CP_COMMIT();
        CP_WAIT0();
        BAR_PAIR(barid);

        float acc[2][4];
#pragma unroll
        for (int f = 0; f < 2; f++)
#pragma unroll
            for (int q = 0; q < 4; q++) acc[f][q] = 0.0f;

#pragma unroll 1
        for (int ks = 0; ks < 4; ks++) {
            const int buf = ks & 1;

            if (ks < 3) {   // prefetch chunk ks+1 into other buffer (pair-local)
                const uint32_t d2 = hdst + (buf ^ 1) * R4_BUF;
                CP_ASYNC16(d2,               HgH + (ks + 1) * 512);
                CP_ASYNC16(d2 + 16,          HgH + (ks + 1) * 512 + 16);
                CP_ASYNC16(d2 + R4_HLO,      HgL + (ks + 1) * 512);
                CP_ASYNC16(d2 + R4_HLO + 16, HgL + (ks + 1) * 512 + 16);
                CP_COMMIT();
            }

            const uint32_t abase = hpair + buf * R4_BUF;
#pragma unroll
            for (int kk = 0; kk < 4; kk++) {
                const uint32_t gkb = ks * 512 + kq * 128 + kk * 32;   // W byte offset
                uint32_t ah[4], al[4];
                uint32_t ad = abase + (lane & 15) * 144 + kk * 32 + (lane >> 4) * 16;
                ldsm4(ah, ad);
                ldsm4(al, ad + R4_HLO);

                uint32_t bh[4], bl[4];
                uint32_t bd = sb + R4_OFFW +
                              (nq * 16 + (lane & 7) + ((lane >> 4) << 3)) * R4_WS +
                              gkb + (((lane >> 3) & 1) << 4);
                ldsm4(bh, bd);
                ldsm4(bl, bd + (R4_OFFWL - R4_OFFW));

#pragma unroll
                for (int f = 0; f < 2; f++) {
                    mma_bf16(acc[f], ah, bh[f * 2], bh[f * 2 + 1]);
                    mma_bf16(acc[f], ah, bl[f * 2], bl[f * 2 + 1]);
                    mma_bf16(acc[f], al, bh[f * 2], bh[f * 2 + 1]);
                }
            }

            if (ks < 3) {
                CP_WAIT0();
                BAR_PAIR(barid);
            }
        }

        // ---- combine 4 k-quarters via smem: group-local 128-thread barriers ----
        if (kq > 0) {
            unsigned char* red = sm + R4_OFFRED + (kq - 1) * R4_REDSL +
                                 (((mq * 2 + nq) * 32 + lane) * 32);
            *(float4*)(red +  0) = make_float4(acc[0][0], acc[0][1], acc[0][2], acc[0][3]);
            *(float4*)(red + 16) = make_float4(acc[1][0], acc[1][1], acc[1][2], acc[1][3]);
            BAR_GRP(gbar);
        } else {
            BAR_GRP(gbar);
#pragma unroll
            for (int s = 0; s < 3; s++) {
                const unsigned char* red = sm + R4_OFFRED + s * R4_REDSL +
                                           (((mq * 2 + nq) * 32 + lane) * 32);
                float4 r0 = *(const float4*)(red +  0);
                float4 r1 = *(const float4*)(red + 16);
                acc[0][0] += r0.x; acc[0][1] += r0.y; acc[0][2] += r0.z; acc[0][3] += r0.w;
                acc[1][0] += r1.x; acc[1][1] += r1.y; acc[1][2] += r1.z; acc[1][3] += r1.w;
            }

            __nv_bfloat16* WH = g_hbf_hi[(t + 1) & 1];
            __nv_bfloat16* WL = g_hbf_lo[(t + 1) & 1];

            float a00 = tanhf(acc[0][0] + xp00.x), a01 = tanhf(acc[0][1] + xp00.y);
            float a80 = tanhf(acc[1][0] + xp01.x), a81 = tanhf(acc[1][1] + xp01.y);
            float b00 = tanhf(acc[0][2] + xp10.x), b01 = tanhf(acc[0][3] + xp10.y);
            float b80 = tanhf(acc[1][2] + xp11.x), b81 = tanhf(acc[1][3] + xp11.y);

            uint32_t ph, pl;
            size_t o00 = (size_t)erow * NDIM + ecol;
            size_t o01 = o00 + 8;
            size_t o10 = (size_t)(erow + 8) * NDIM + ecol;
            size_t o11 = o10 + 8;
            split2(a00, a01, ph, pl); *(uint32_t*)&WH[o00] = ph; *(uint32_t*)&WL[o00] = pl;
            split2(a80, a81, ph, pl); *(uint32_t*)&WH[o01] = ph; *(uint32_t*)&WL[o01] = pl;
            split2(b00, b01, ph, pl); *(uint32_t*)&WH[o10] = ph; *(uint32_t*)&WL[o10] = pl;
            split2(b80, b81, ph, pl); *(uint32_t*)&WH[o11] = ph; *(uint32_t*)&WL[o11] = pl;

            if (t == SEQ - 1) {
                *(float2*)(g_hfin + o00) = make_float2(a00, a01);
                *(float2*)(g_hfin + o01) = make_float2(a80, a81);
                *(float2*)(g_hfin + o10) = make_float2(b00, b01);
                *(float2*)(g_hfin + o11) = make_float2(b80, b81);
            }

            // publish h(t+1): only the 4 epilogue warps need to converge.
            asm volatile("bar.sync 15, 128;" ::: "memory");
            if (tid == 0) {
                __threadfence();
                atomicAdd(&g_sflag[mi][nj], 1u);
            }
        }
        // kq>0 warps: no further convergence — next step's flag wait (which
        // includes own CTA's flag, published after the kq=0 red reads)
        // transitively orders red-area reuse and h-buffer reuse.
    }
}

// ---------------------------------------------------------------------------
// Final: out = h_final @ W_hy + b_y
// ---------------------------------------------------------------------------
__global__ void __launch_bounds__(128) rnn_final(const float* __restrict__ W,
                                                 const float* __restrict__ bias,
                                                 float* __restrict__ out) {
    __shared__ float As[32 * 34];
    __shared__ float Bs[32 * 32];

    const float* __restrict__ H = g_hfin;

    const int tid = threadIdx.x;
    const int bx  = blockIdx.x;
    const int by  = blockIdx.y;

    const int rI = tid / 8;
    const int cI = (tid % 8) * 4;
    const int tr = tid / 8;
    const int tc = tid % 8;

    float acc[2][4];
#pragma unroll
    for (int i = 0; i < 2; i++)
#pragma unroll
        for (int q = 0; q < 4; q++) acc[i][q] = 0.0f;

    for (int bk = 0; bk < NDIM; bk += 32) {
#pragma unroll
        for (int rr = 0; rr < 2; rr++) {
            int rw = rI + rr * 16;
            float4 a = *(const float4*)(H + (by * 32 + rw) * NDIM + bk + cI);
            As[(cI + 0) * 34 + rw] = a.x;
            As[(cI + 1) * 34 + rw] = a.y;
            As[(cI + 2) * 34 + rw] = a.z;
            As[(cI + 3) * 34 + rw] = a.w;
            *(float4*)(Bs + rw * 32 + cI) =
                *(const float4*)(W + (size_t)(bk + rw) * NDIM + bx * 32 + cI);
        }
        __syncthreads();

#pragma unroll
        for (int k = 0; k < 32; k++) {
            float2 av = *(const float2*)(As + k * 34 + tr * 2);
            float4 bv = *(const float4*)(Bs + k * 32 + tc * 4);
            acc[0][0] += av.x * bv.x; acc[0][1] += av.x * bv.y;
            acc[0][2] += av.x * bv.z; acc[0][3] += av.x * bv.w;
            acc[1][0] += av.y * bv.x; acc[1][1] += av.y * bv.y;
            acc[1][2] += av.y * bv.z; acc[1][3] += av.y * bv.w;
        }
        __syncthreads();
    }

    const int col = bx * 32 + tc * 4;
    float4 bv4 = *(const float4*)(bias + col);
#pragma unroll
    for (int i = 0; i < 2; i++) {
        int row = by * 32 + tr * 2 + i;
        float4 v;
        v.x = acc[i][0] + bv4.x;
        v.y = acc[i][1] + bv4.y;
        v.z = acc[i][2] + bv4.z;
        v.w = acc[i][3] + bv4.w;
        *(float4*)(out + row * NDIM + col) = v;
    }
}

// ---------------------------------------------------------------------------
// kernel_launch — graph-capturable
// ---------------------------------------------------------------------------
extern "C" void kernel_launch(void* const* d_in, const int* in_sizes, int n_in,
                              void* d_out, int out_size) {
    (void)in_sizes; (void)n_in; (void)out_size;
    const float* x    = (const float*)d_in[0];
    const float* W_xh = (const float*)d_in[1];
    const float* W_hh = (const float*)d_in[2];
    const float* b_h  = (const float*)d_in[3];
    const float* W_hy = (const float*)d_in[4];
    const float* b_y  = (const float*)d_in[5];
    float* out = (float*)d_out;

    cudaFuncSetAttribute(xp_gemm_mma, cudaFuncAttributeMaxDynamicSharedMemorySize, XP_SMEM);
    cudaFuncSetAttribute(rnn_persistent11, cudaFuncAttributeMaxDynamicSharedMemorySize, R4_SMEM);

    zero_hbf<<<(BATCH * NDIM + 511) / 512, 512>>>();

    dim3 gridW(NDIM / 32, NDIM / 32, 2);            // both weight preps in one launch
    wprep<<<gridW, dim3(32, 8)>>>(W_xh, W_hh);

    dim3 gridXP(NDIM / 128, (BATCH * SEQ) / 128);   // (8, 512)
    xp_gemm_mma<<<gridXP, 256, XP_SMEM>>>(x, b_h);

    rnn_persistent11<<<RGRID, 512, R4_SMEM>>>();

    dim3 gridFin(NDIM / 32, BATCH / 32);
    rnn_final<<<gridFin, 128>>>(W_hy, b_y, out);
}

// round 15
// speedup vs baseline: 1.0195x; 1.0195x over previous
#include <cuda_runtime.h>
#include <cuda_bf16.h>
#include <math.h>
#include <stdint.h>

#define BATCH 128
#define SEQ   512
#define NDIM  1024
#define RGRID 128          // persistent CTAs: 4 m-groups x 32 n-blocks

// ---------------------------------------------------------------------------
// Global scratch (allocation-free)
// ---------------------------------------------------------------------------
__device__ float g_xp[(size_t)BATCH * SEQ * NDIM];        // 256 MB
__device__ __nv_bfloat16 g_Wt_hi[(size_t)NDIM * NDIM];    // W_xh^T hi  [N][K]
__device__ __nv_bfloat16 g_Wt_lo[(size_t)NDIM * NDIM];
__device__ __nv_bfloat16 g_Whh_hi[(size_t)NDIM * NDIM];   // W_hh^T hi  [N][K]
__device__ __nv_bfloat16 g_Whh_lo[(size_t)NDIM * NDIM];
__device__ __nv_bfloat16 g_hbf_hi[2][BATCH * NDIM];       // ping-pong h hi
__device__ __nv_bfloat16 g_hbf_lo[2][BATCH * NDIM];       // ping-pong h lo
__device__ float g_hfin[BATCH * NDIM];                    // final h fp32
__device__ unsigned g_gcnt[4 * 32];                       // init-barrier counters
__device__ unsigned g_ggen[4 * 32];                       // init-barrier generations
__device__ __align__(128) unsigned g_sflag[4][32];        // per-CTA step flags (1 line/group)

// ---------------------------------------------------------------------------
// Helpers
// ---------------------------------------------------------------------------
__device__ __forceinline__ uint32_t smem_u32(const void* p) {
    uint32_t a;
    asm("{ .reg .u64 t; cvta.to.shared.u64 t, %1; cvt.u32.u64 %0, t; }"
        : "=r"(a) : "l"(p));
    return a;
}

__device__ __forceinline__ void ldsm4(uint32_t (&r)[4], uint32_t addr) {
    asm volatile("ldmatrix.sync.aligned.m8n8.x4.shared.b16 {%0,%1,%2,%3}, [%4];"
                 : "=r"(r[0]), "=r"(r[1]), "=r"(r[2]), "=r"(r[3]) : "r"(addr));
}

__device__ __forceinline__ void mma_bf16(float (&d)[4], const uint32_t (&a)[4],
                                         const uint32_t b0, const uint32_t b1) {
    asm volatile(
        "mma.sync.aligned.m16n8k16.row.col.f32.bf16.bf16.f32 "
        "{%0,%1,%2,%3}, {%4,%5,%6,%7}, {%8,%9}, {%0,%1,%2,%3};"
        : "+f"(d[0]), "+f"(d[1]), "+f"(d[2]), "+f"(d[3])
        : "r"(a[0]), "r"(a[1]), "r"(a[2]), "r"(a[3]), "r"(b0), "r"(b1));
}

#define CP_ASYNC16(dst, src) \
    asm volatile("cp.async.cg.shared.global [%0], [%1], 16;" \
                 :: "r"(dst), "l"(src) : "memory")
#define CP_COMMIT() asm volatile("cp.async.commit_group;" ::: "memory")
#define CP_WAIT0()  asm volatile("cp.async.wait_group 0;" ::: "memory")
#define BAR_PAIR(id) asm volatile("bar.sync %0, 64;" :: "r"(id) : "memory")

// fast tanh: t = exp(-2|x|) in (0,1] (no overflow), r = sign(x)*(1-t)/(1+t)
__device__ __forceinline__ float tanh_fast(float x) {
    float t = __expf(-2.0f * fabsf(x));
    float r = 1.0f - __fdividef(2.0f * t, 1.0f + t);
    return copysignf(r, x);
}

// split 8 fp32 -> 8 bf16 hi + 8 bf16 lo (packed uint4 each)
__device__ __forceinline__ void split8(float4 f0, float4 f1, uint4& hi, uint4& lo) {
    float f[8] = {f0.x, f0.y, f0.z, f0.w, f1.x, f1.y, f1.z, f1.w};
    unsigned short h[8], l[8];
#pragma unroll
    for (int i = 0; i < 8; i++) {
        __nv_bfloat16 bh = __float2bfloat16_rn(f[i]);
        float r = f[i] - __bfloat162float(bh);
        h[i] = __bfloat16_as_ushort(bh);
        l[i] = __bfloat16_as_ushort(__float2bfloat16_rn(r));
    }
    hi.x = (uint32_t)h[0] | ((uint32_t)h[1] << 16);
    hi.y = (uint32_t)h[2] | ((uint32_t)h[3] << 16);
    hi.z = (uint32_t)h[4] | ((uint32_t)h[5] << 16);
    hi.w = (uint32_t)h[6] | ((uint32_t)h[7] << 16);
    lo.x = (uint32_t)l[0] | ((uint32_t)l[1] << 16);
    lo.y = (uint32_t)l[2] | ((uint32_t)l[3] << 16);
    lo.z = (uint32_t)l[4] | ((uint32_t)l[5] << 16);
    lo.w = (uint32_t)l[6] | ((uint32_t)l[7] << 16);
}

// split 2 fp32 -> packed bf16x2 hi + lo
__device__ __forceinline__ void split2(float a, float b, uint32_t& hi, uint32_t& lo) {
    __nv_bfloat16 ah = __float2bfloat16_rn(a), bh = __float2bfloat16_rn(b);
    float ar = a - __bfloat162float(ah), br = b - __bfloat162float(bh);
    hi = (uint32_t)__bfloat16_as_ushort(ah) |
         ((uint32_t)__bfloat16_as_ushort(bh) << 16);
    lo = (uint32_t)__bfloat16_as_ushort(__float2bfloat16_rn(ar)) |
         ((uint32_t)__bfloat16_as_ushort(__float2bfloat16_rn(br)) << 16);
}

// one-time 32-CTA group barrier (replay-safe, monotonic generation)
__device__ __forceinline__ void group_barrier(int grp) {
    __syncthreads();
    if (threadIdx.x == 0) {
        unsigned* cnt = &g_gcnt[grp * 32];
        volatile unsigned* gen = (volatile unsigned*)&g_ggen[grp * 32];
        unsigned myg = *gen;
        __threadfence();
        if (atomicAdd(cnt, 1) == 31) {
            atomicExch(cnt, 0);
            __threadfence();
            atomicAdd((unsigned*)gen, 1);
        } else {
            while (*gen == myg) { }
            __threadfence();
        }
    }
    __syncthreads();
}

// ---------------------------------------------------------------------------
// Setup kernels
// ---------------------------------------------------------------------------
__global__ void zero_hbf() {
    int idx = blockIdx.x * blockDim.x + threadIdx.x;
    if (idx < BATCH * NDIM) {
        g_hbf_hi[0][idx] = __float2bfloat16_rn(0.0f);
        g_hbf_lo[0][idx] = __float2bfloat16_rn(0.0f);
    }
}

// Transpose + split W [K,N] -> dst_hi/lo [N,K] bf16.  blockIdx.z: 0=W_xh, 1=W_hh
__global__ void wprep(const float* __restrict__ Wxh, const float* __restrict__ Whh) {
    __shared__ float t[32][33];
    const int which = blockIdx.z;
    const float* W = which ? Whh : Wxh;
    __nv_bfloat16* dhi = which ? g_Whh_hi : g_Wt_hi;
    __nv_bfloat16* dlo = which ? g_Whh_lo : g_Wt_lo;
    int tx = threadIdx.x, ty = threadIdx.y;
    int nb = blockIdx.x * 32, kb = blockIdx.y * 32;
#pragma unroll
    for (int i = ty; i < 32; i += 8)
        t[i][tx] = W[(size_t)(kb + i) * NDIM + nb + tx];
    __syncthreads();
#pragma unroll
    for (int i = ty; i < 32; i += 8) {
        float f = t[tx][i];
        __nv_bfloat16 bh = __float2bfloat16_rn(f);
        float r = f - __bfloat162float(bh);
        size_t off = (size_t)(nb + i) * NDIM + kb + tx;
        dhi[off] = bh;
        dlo[off] = __float2bfloat16_rn(r);
    }
}

// ---------------------------------------------------------------------------
// XP GEMM via mma.sync bf16-split (unchanged)
// ---------------------------------------------------------------------------
#define XP_ARR  10240
#define XP_BUF  (4 * XP_ARR)
#define XP_SMEM (2 * XP_BUF)

__global__ void __launch_bounds__(256) xp_gemm_mma(const float* __restrict__ A,
                                                   const float* __restrict__ bias) {
    extern __shared__ __align__(16) unsigned char sm[];
    const uint32_t sb = smem_u32(sm);
    const int tid = threadIdx.x, wid = tid >> 5, lane = tid & 31;
    const int cCol = blockIdx.x, cRow = blockIdx.y;
    const int wm = (wid >> 2) * 64;
    const int wn = (wid & 3) * 32;

    const int lrow = tid >> 1;
    const int lhf  = tid & 1;
    const float* Ag = A + (size_t)(cRow * 128 + lrow) * NDIM + lhf * 16;
    const __nv_bfloat16* Bhg = g_Wt_hi + (size_t)(cCol * 128 + lrow) * NDIM + lhf * 16;
    const __nv_bfloat16* Blg = g_Wt_lo + (size_t)(cCol * 128 + lrow) * NDIM + lhf * 16;
    unsigned char* st_a = sm + lrow * 80 + lhf * 32;
    unsigned char* st_b = sm + 2 * XP_ARR + lrow * 80 + lhf * 32;

    float acc[4][4][4];
#pragma unroll
    for (int i = 0; i < 4; i++)
#pragma unroll
        for (int j = 0; j < 4; j++)
#pragma unroll
            for (int q = 0; q < 4; q++) acc[i][j][q] = 0.0f;

    {
        float4 f0 = *(const float4*)(Ag + 0);
        float4 f1 = *(const float4*)(Ag + 4);
        float4 f2 = *(const float4*)(Ag + 8);
        float4 f3 = *(const float4*)(Ag + 12);
        uint4 h0, l0, h1, l1;
        split8(f0, f1, h0, l0);
        split8(f2, f3, h1, l1);
        *(uint4*)(st_a +  0) = h0; *(uint4*)(st_a + 16) = h1;
        *(uint4*)(st_a + XP_ARR +  0) = l0; *(uint4*)(st_a + XP_ARR + 16) = l1;
        uint4 bh0 = *(const uint4*)(Bhg);     uint4 bh1 = *(const uint4*)(Bhg + 8);
        uint4 bl0 = *(const uint4*)(Blg);     uint4 bl1 = *(const uint4*)(Blg + 8);
        *(uint4*)(st_b +  0) = bh0; *(uint4*)(st_b + 16) = bh1;
        *(uint4*)(st_b + XP_ARR +  0) = bl0; *(uint4*)(st_b + XP_ARR + 16) = bl1;
    }
    __syncthreads();

#pragma unroll 1
    for (int ko = 0; ko < 32; ko++) {
        const int buf = ko & 1;
        float4 f0, f1, f2, f3;
        uint4 pbh0, pbh1, pbl0, pbl1;
        if (ko < 31) {
            const float* Ap = Ag + (ko + 1) * 32;
            f0 = *(const float4*)(Ap + 0);  f1 = *(const float4*)(Ap + 4);
            f2 = *(const float4*)(Ap + 8);  f3 = *(const float4*)(Ap + 12);
            pbh0 = *(const uint4*)(Bhg + (ko + 1) * 32);
            pbh1 = *(const uint4*)(Bhg + (ko + 1) * 32 + 8);
            pbl0 = *(const uint4*)(Blg + (ko + 1) * 32);
            pbl1 = *(const uint4*)(Blg + (ko + 1) * 32 + 8);
        }

        const uint32_t base = sb + buf * XP_BUF;
#pragma unroll
        for (int s = 0; s < 2; s++) {
            const uint32_t k0b = s * 32;
            uint32_t ah[4][4], al[4][4];
#pragma unroll
            for (int mi = 0; mi < 4; mi++) {
                uint32_t ad = base + (wm + mi * 16 + (lane & 15)) * 80 + k0b + (lane >> 4) * 16;
                ldsm4(ah[mi], ad);
                ldsm4(al[mi], ad + XP_ARR);
            }
            uint32_t bh[4][2], bl[4][2];
#pragma unroll
            for (int nb = 0; nb < 2; nb++) {
                uint32_t bd = base + 2 * XP_ARR +
                              (wn + nb * 16 + (lane & 7) + ((lane >> 4) << 3)) * 80 +
                              k0b + (((lane >> 3) & 1) << 4);
                uint32_t r[4];
                ldsm4(r, bd);
                bh[nb * 2 + 0][0] = r[0]; bh[nb * 2 + 0][1] = r[1];
                bh[nb * 2 + 1][0] = r[2]; bh[nb * 2 + 1][1] = r[3];
                ldsm4(r, bd + XP_ARR);
                bl[nb * 2 + 0][0] = r[0]; bl[nb * 2 + 0][1] = r[1];
                bl[nb * 2 + 1][0] = r[2]; bl[nb * 2 + 1][1] = r[3];
            }
#pragma unroll
            for (int mi = 0; mi < 4; mi++)
#pragma unroll
                for (int nj = 0; nj < 4; nj++) {
                    mma_bf16(acc[mi][nj], ah[mi], bh[nj][0], bh[nj][1]);
                    mma_bf16(acc[mi][nj], ah[mi], bl[nj][0], bl[nj][1]);
                    mma_bf16(acc[mi][nj], al[mi], bh[nj][0], bh[nj][1]);
                }
        }

        if (ko < 31) {
            unsigned char* da = st_a + (buf ^ 1) * XP_BUF;
            unsigned char* db = st_b + (buf ^ 1) * XP_BUF;
            uint4 h0, l0, h1, l1;
            split8(f0, f1, h0, l0);
            split8(f2, f3, h1, l1);
            *(uint4*)(da +  0) = h0; *(uint4*)(da + 16) = h1;
            *(uint4*)(da + XP_ARR +  0) = l0; *(uint4*)(da + XP_ARR + 16) = l1;
            *(uint4*)(db +  0) = pbh0; *(uint4*)(db + 16) = pbh1;
            *(uint4*)(db + XP_ARR +  0) = pbl0; *(uint4*)(db + XP_ARR + 16) = pbl1;
            __syncthreads();
        }
    }

#pragma unroll
    for (int mi = 0; mi < 4; mi++) {
        int row = cRow * 128 + wm + mi * 16 + (lane >> 2);
#pragma unroll
        for (int nj = 0; nj < 4; nj++) {
            int col = cCol * 128 + wn + nj * 8 + (lane & 3) * 2;
            float b0 = bias[col], b1 = bias[col + 1];
            float2 v0 = {acc[mi][nj][0] + b0, acc[mi][nj][1] + b1};
            float2 v1 = {acc[mi][nj][2] + b0, acc[mi][nj][3] + b1};
            *(float2*)(g_xp + (size_t)row * NDIM + col) = v0;
            *(float2*)(g_xp + (size_t)(row + 8) * NDIM + col) = v1;
        }
    }
}

// ---------------------------------------------------------------------------
// Persistent recurrence v12: exact R13 winner (per-pair h staging, block
// syncthreads combine) + two critical-path cuts:
//   (a) ks=0 W fragments register-cached (step-invariant; peeled iteration)
//   (b) fast tanh (expf-based, ~9 instrs, no overflow)
// ---------------------------------------------------------------------------
#define R4_WS     2064
#define R4_OFFW   0
#define R4_OFFWL  66048
#define R4_OFFH   132096
#define R4_PAIR   9216                 // per pair: 2 bufs x (hi 2304 + lo 2304)
#define R4_BUF    4608
#define R4_HLO    2304
#define R4_OFFRED (132096 + 8 * 9216)  // 205824
#define R4_REDSL  4096
#define R4_SMEM   (205824 + 3 * 4096)  // 218112

__global__ void __launch_bounds__(512) rnn_persistent12() {
    extern __shared__ __align__(16) unsigned char sm[];
    const uint32_t sb = smem_u32(sm);
    const int tid = threadIdx.x, wid = tid >> 5, lane = tid & 31;
    const int r  = blockIdx.x;
    const int mi = r >> 5;          // m-group 0..3
    const int nj = r & 31;          // n-block 0..31
    const int mq = (wid >> 1) & 1;  // quadrant m
    const int nq = wid & 1;         // quadrant n
    const int kq = wid >> 2;        // k-quarter 0..3
    const int pair = wid >> 1;      // 0..7 : (kq, mq) pair shared by nq=0,1
    const int barid = 1 + pair;     // named barrier ids 1..8 (15 = epilogue)

    // snapshot my lane's flag base BEFORE anyone publishes (replay-safe)
    const unsigned fbase = *((volatile unsigned*)&g_sflag[mi][lane]);
    const unsigned* fptr = &g_sflag[mi][lane];

    // ---- load W_hh^T rows [nj*32, +32) into smem (once, persistent) ----
    {
        const int n  = tid >> 4;             // 0..31
        const int sg = (tid & 15) * 128;     // byte offset within 2048B row
        const unsigned char* gh = (const unsigned char*)(g_Whh_hi + (size_t)(nj * 32 + n) * NDIM) + sg;
        const unsigned char* gl = (const unsigned char*)(g_Whh_lo + (size_t)(nj * 32 + n) * NDIM) + sg;
        uint32_t dh = sb + R4_OFFW  + n * R4_WS + sg;
        uint32_t dl = sb + R4_OFFWL + n * R4_WS + sg;
#pragma unroll
        for (int i = 0; i < 8; i++) {
            CP_ASYNC16(dh + i * 16, gh + i * 16);
            CP_ASYNC16(dl + i * 16, gl + i * 16);
        }
        CP_COMMIT();
    }

    group_barrier(mi);   // all snapshots taken; safe to start publishing

    // pair-local h loader geometry: 64 threads cover 16 rows x 128B
    const int ptid = nq * 32 + lane;        // 0..63 within pair
    const int prow = ptid >> 2;             // 0..15
    const int pseg = (ptid & 3) * 32;       // 0,32,64,96
    const uint32_t hpair = sb + R4_OFFH + pair * R4_PAIR;
    const uint32_t hdst  = hpair + prow * 144 + pseg;   // +buf*R4_BUF, lo +R4_HLO

    // epilogue geometry (kq==0 warps, wid 0..3)
    const int erow = mi * 32 + mq * 16 + (lane >> 2);
    const int ecol = nj * 32 + nq * 16 + (lane & 3) * 2;

    CP_WAIT0();
    __syncthreads();

    // ---- register-cache ks=0 W fragments (step-invariant) ----
    uint32_t wc_bh[4][4], wc_bl[4][4];
#pragma unroll
    for (int kk = 0; kk < 4; kk++) {
        uint32_t bd = sb + R4_OFFW +
                      (nq * 16 + (lane & 7) + ((lane >> 4) << 3)) * R4_WS +
                      (kq * 128 + kk * 32) + (((lane >> 3) & 1) << 4);
        ldsm4(wc_bh[kk], bd);
        ldsm4(wc_bl[kk], bd + (R4_OFFWL - R4_OFFW));
    }

#pragma unroll 1
    for (int t = 0; t < SEQ; t++) {
        // per-thread global h source: row mi*32+mq*16+prow, col window kq*128+pseg
        const unsigned char* HgH =
            (const unsigned char*)(g_hbf_hi[t & 1] + (size_t)(mi * 32 + mq * 16 + prow) * NDIM)
            + kq * 128 + pseg;
        const unsigned char* HgL =
            (const unsigned char*)(g_hbf_lo[t & 1] + (size_t)(mi * 32 + mq * 16 + prow) * NDIM)
            + kq * 128 + pseg;

        // xp prefetch (epilogue warps) — before any waiting
        float2 xp00, xp01, xp10, xp11;
        if (kq == 0) {
            const float* b0 = g_xp + ((size_t)erow * SEQ + t) * NDIM;
            const float* b1 = g_xp + ((size_t)(erow + 8) * SEQ + t) * NDIM;
            xp00 = *(const float2*)(b0 + ecol);
            xp01 = *(const float2*)(b0 + ecol + 8);
            xp10 = *(const float2*)(b1 + ecol);
            xp11 = *(const float2*)(b1 + ecol + 8);
        }

        // ---- wait: all 32 producers of h(t) published (acquire-load poll) ----
        if (t > 0) {
            const unsigned target = fbase + (unsigned)t;
            unsigned v;
            do {
                asm volatile("ld.global.acquire.gpu.b32 %0, [%1];"
                             : "=r"(v) : "l"(fptr) : "memory");
            } while (!__all_sync(0xFFFFFFFFu, (int)(v - target) >= 0));
        }

        // prologue: chunk 0 -> buf 0 (pair-local, 64-thread barrier)
        CP_ASYNC16(hdst,                HgH);
        CP_ASYNC16(hdst + 16,           HgH + 16);
        CP_ASYNC16(hdst + R4_HLO,       HgL);
        CP_ASYNC16(hdst + R4_HLO + 16,  HgL + 16);
        CP_COMMIT();
        CP_WAIT0();
        BAR_PAIR(barid);

        float acc[2][4];
#pragma unroll
        for (int f = 0; f < 2; f++)
#pragma unroll
            for (int q = 0; q < 4; q++) acc[f][q] = 0.0f;

        // ---- ks = 0 (peeled: W from registers) ----
        {
            // prefetch chunk 1 into buffer 1 (pair-local)
            const uint32_t d2 = hdst + R4_BUF;
            CP_ASYNC16(d2,               HgH + 512);
            CP_ASYNC16(d2 + 16,          HgH + 512 + 16);
            CP_ASYNC16(d2 + R4_HLO,      HgL + 512);
            CP_ASYNC16(d2 + R4_HLO + 16, HgL + 512 + 16);
            CP_COMMIT();

#pragma unroll
            for (int kk = 0; kk < 4; kk++) {
                uint32_t ah[4], al[4];
                uint32_t ad = hpair + (lane & 15) * 144 + kk * 32 + (lane >> 4) * 16;
                ldsm4(ah, ad);
                ldsm4(al, ad + R4_HLO);
#pragma unroll
                for (int f = 0; f < 2; f++) {
                    mma_bf16(acc[f], ah, wc_bh[kk][f * 2], wc_bh[kk][f * 2 + 1]);
                    mma_bf16(acc[f], ah, wc_bl[kk][f * 2], wc_bl[kk][f * 2 + 1]);
                    mma_bf16(acc[f], al, wc_bh[kk][f * 2], wc_bh[kk][f * 2 + 1]);
                }
            }
            CP_WAIT0();
            BAR_PAIR(barid);
        }

        // ---- ks = 1..3 (W via ldsm) ----
#pragma unroll 1
        for (int ks = 1; ks < 4; ks++) {
            const int buf = ks & 1;

            if (ks < 3) {   // prefetch chunk ks+1 into other buffer (pair-local)
                const uint32_t d2 = hdst + (buf ^ 1) * R4_BUF;
                CP_ASYNC16(d2,               HgH + (ks + 1) * 512);
                CP_ASYNC16(d2 + 16,          HgH + (ks + 1) * 512 + 16);
                CP_ASYNC16(d2 + R4_HLO,      HgL + (ks + 1) * 512);
                CP_ASYNC16(d2 + R4_HLO + 16, HgL + (ks + 1) * 512 + 16);
                CP_COMMIT();
            }

            const uint32_t abase = hpair + buf * R4_BUF;
#pragma unroll
            for (int kk = 0; kk < 4; kk++) {
                const uint32_t gkb = ks * 512 + kq * 128 + kk * 32;   // W byte offset
                uint32_t ah[4], al[4];
                uint32_t ad = abase + (lane & 15) * 144 + kk * 32 + (lane >> 4) * 16;
                ldsm4(ah, ad);
                ldsm4(al, ad + R4_HLO);

                uint32_t bh[4], bl[4];
                uint32_t bd = sb + R4_OFFW +
                              (nq * 16 + (lane & 7) + ((lane >> 4) << 3)) * R4_WS +
                              gkb + (((lane >> 3) & 1) << 4);
                ldsm4(bh, bd);
                ldsm4(bl, bd + (R4_OFFWL - R4_OFFW));

#pragma unroll
                for (int f = 0; f < 2; f++) {
                    mma_bf16(acc[f], ah, bh[f * 2], bh[f * 2 + 1]);
                    mma_bf16(acc[f], ah, bl[f * 2], bl[f * 2 + 1]);
                    mma_bf16(acc[f], al, bh[f * 2], bh[f * 2 + 1]);
                }
            }

            if (ks < 3) {
                CP_WAIT0();
                BAR_PAIR(barid);
            }
        }

        // ---- combine 4 k-quarters via smem (block-wide, 1 syncthreads) ----
        if (kq > 0) {
            unsigned char* red = sm + R4_OFFRED + (kq - 1) * R4_REDSL +
                                 (((mq * 2 + nq) * 32 + lane) * 32);
            *(float4*)(red +  0) = make_float4(acc[0][0], acc[0][1], acc[0][2], acc[0][3]);
            *(float4*)(red + 16) = make_float4(acc[1][0], acc[1][1], acc[1][2], acc[1][3]);
        }
        __syncthreads();

        if (kq == 0) {
#pragma unroll
            for (int s = 0; s < 3; s++) {
                const unsigned char* red = sm + R4_OFFRED + s * R4_REDSL +
                                           (((mq * 2 + nq) * 32 + lane) * 32);
                float4 r0 = *(const float4*)(red +  0);
                float4 r1 = *(const float4*)(red + 16);
                acc[0][0] += r0.x; acc[0][1] += r0.y; acc[0][2] += r0.z; acc[0][3] += r0.w;
                acc[1][0] += r1.x; acc[1][1] += r1.y; acc[1][2] += r1.z; acc[1][3] += r1.w;
            }

            __nv_bfloat16* WH = g_hbf_hi[(t + 1) & 1];
            __nv_bfloat16* WL = g_hbf_lo[(t + 1) & 1];

            float a00 = tanh_fast(acc[0][0] + xp00.x), a01 = tanh_fast(acc[0][1] + xp00.y);
            float a80 = tanh_fast(acc[1][0] + xp01.x), a81 = tanh_fast(acc[1][1] + xp01.y);
            float b00 = tanh_fast(acc[0][2] + xp10.x), b01 = tanh_fast(acc[0][3] + xp10.y);
            float b80 = tanh_fast(acc[1][2] + xp11.x), b81 = tanh_fast(acc[1][3] + xp11.y);

            uint32_t ph, pl;
            size_t o00 = (size_t)erow * NDIM + ecol;
            size_t o01 = o00 + 8;
            size_t o10 = (size_t)(erow + 8) * NDIM + ecol;
            size_t o11 = o10 + 8;
            split2(a00, a01, ph, pl); *(uint32_t*)&WH[o00] = ph; *(uint32_t*)&WL[o00] = pl;
            split2(a80, a81, ph, pl); *(uint32_t*)&WH[o01] = ph; *(uint32_t*)&WL[o01] = pl;
            split2(b00, b01, ph, pl); *(uint32_t*)&WH[o10] = ph; *(uint32_t*)&WL[o10] = pl;
            split2(b80, b81, ph, pl); *(uint32_t*)&WH[o11] = ph; *(uint32_t*)&WL[o11] = pl;

            // publish h(t+1): only the 4 epilogue warps need to converge.
            asm volatile("bar.sync 15, 128;" ::: "memory");
            if (tid == 0) {
                __threadfence();
                atomicAdd(&g_sflag[mi][nj], 1u);
            }

            if (t == SEQ - 1) {
                *(float2*)(g_hfin + o00) = make_float2(a00, a01);
                *(float2*)(g_hfin + o01) = make_float2(a80, a81);
                *(float2*)(g_hfin + o10) = make_float2(b00, b01);
                *(float2*)(g_hfin + o11) = make_float2(b80, b81);
            }
        }
        // warps 4..15: no final full-CTA barrier — next step's flag wait
        // (which includes own CTA's flag) transitively orders everything.
    }
}

// ---------------------------------------------------------------------------
// Final: out = h_final @ W_hy + b_y
// ---------------------------------------------------------------------------
__global__ void __launch_bounds__(128) rnn_final(const float* __restrict__ W,
                                                 const float* __restrict__ bias,
                                                 float* __restrict__ out) {
    __shared__ float As[32 * 34];
    __shared__ float Bs[32 * 32];

    const float* __restrict__ H = g_hfin;

    const int tid = threadIdx.x;
    const int bx  = blockIdx.x;
    const int by  = blockIdx.y;

    const int rI = tid / 8;
    const int cI = (tid % 8) * 4;
    const int tr = tid / 8;
    const int tc = tid % 8;

    float acc[2][4];
#pragma unroll
    for (int i = 0; i < 2; i++)
#pragma unroll
        for (int q = 0; q < 4; q++) acc[i][q] = 0.0f;

    for (int bk = 0; bk < NDIM; bk += 32) {
#pragma unroll
        for (int rr = 0; rr < 2; rr++) {
            int rw = rI + rr * 16;
            float4 a = *(const float4*)(H + (by * 32 + rw) * NDIM + bk + cI);
            As[(cI + 0) * 34 + rw] = a.x;
            As[(cI + 1) * 34 + rw] = a.y;
            As[(cI + 2) * 34 + rw] = a.z;
            As[(cI + 3) * 34 + rw] = a.w;
            *(float4*)(Bs + rw * 32 + cI) =
                *(const float4*)(W + (size_t)(bk + rw) * NDIM + bx * 32 + cI);
        }
        __syncthreads();

#pragma unroll
        for (int k = 0; k < 32; k++) {
            float2 av = *(const float2*)(As + k * 34 + tr * 2);
            float4 bv = *(const float4*)(Bs + k * 32 + tc * 4);
            acc[0][0] += av.x * bv.x; acc[0][1] += av.x * bv.y;
            acc[0][2] += av.x * bv.z; acc[0][3] += av.x * bv.w;
            acc[1][0] += av.y * bv.x; acc[1][1] += av.y * bv.y;
            acc[1][2] += av.y * bv.z; acc[1][3] += av.y * bv.w;
        }
        __syncthreads();
    }

    const int col = bx * 32 + tc * 4;
    float4 bv4 = *(const float4*)(bias + col);
#pragma unroll
    for (int i = 0; i < 2; i++) {
        int row = by * 32 + tr * 2 + i;
        float4 v;
        v.x = acc[i][0] + bv4.x;
        v.y = acc[i][1] + bv4.y;
        v.z = acc[i][2] + bv4.z;
        v.w = acc[i][3] + bv4.w;
        *(float4*)(out + row * NDIM + col) = v;
    }
}

// ---------------------------------------------------------------------------
// kernel_launch — graph-capturable
// ---------------------------------------------------------------------------
extern "C" void kernel_launch(void* const* d_in, const int* in_sizes, int n_in,
                              void* d_out, int out_size) {
    (void)in_sizes; (void)n_in; (void)out_size;
    const float* x    = (const float*)d_in[0];
    const float* W_xh = (const float*)d_in[1];
    const float* W_hh = (const float*)d_in[2];
    const float* b_h  = (const float*)d_in[3];
    const float* W_hy = (const float*)d_in[4];
    const float* b_y  = (const float*)d_in[5];
    float* out = (float*)d_out;

    cudaFuncSetAttribute(xp_gemm_mma, cudaFuncAttributeMaxDynamicSharedMemorySize, XP_SMEM);
    cudaFuncSetAttribute(rnn_persistent12, cudaFuncAttributeMaxDynamicSharedMemorySize, R4_SMEM);

    zero_hbf<<<(BATCH * NDIM + 511) / 512, 512>>>();

    dim3 gridW(NDIM / 32, NDIM / 32, 2);            // both weight preps in one launch
    wprep<<<gridW, dim3(32, 8)>>>(W_xh, W_hh);

    dim3 gridXP(NDIM / 128, (BATCH * SEQ) / 128);   // (8, 512)
    xp_gemm_mma<<<gridXP, 256, XP_SMEM>>>(x, b_h);

    rnn_persistent12<<<RGRID, 512, R4_SMEM>>>();

    dim3 gridFin(NDIM / 32, BATCH / 32);
    rnn_final<<<gridFin, 128>>>(W_hy, b_y, out);
}

// round 16
// speedup vs baseline: 1.0268x; 1.0072x over previous
#include <cuda_runtime.h>
#include <cuda_bf16.h>
#include <math.h>
#include <stdint.h>

#define BATCH 128
#define SEQ   512
#define NDIM  1024
#define RGRID 128          // persistent CTAs: 4 m-groups x 32 n-blocks

// ---------------------------------------------------------------------------
// Global scratch (allocation-free)
// ---------------------------------------------------------------------------
__device__ float g_xp[(size_t)BATCH * SEQ * NDIM];        // 256 MB
__device__ __nv_bfloat16 g_Wt_hi[(size_t)NDIM * NDIM];    // W_xh^T hi  [N][K]
__device__ __nv_bfloat16 g_Wt_lo[(size_t)NDIM * NDIM];
__device__ __nv_bfloat16 g_Whh_hi[(size_t)NDIM * NDIM];   // W_hh^T hi  [N][K]
__device__ __nv_bfloat16 g_Whh_lo[(size_t)NDIM * NDIM];
__device__ __nv_bfloat16 g_hbf_hi[2][BATCH * NDIM];       // ping-pong h hi
__device__ __nv_bfloat16 g_hbf_lo[2][BATCH * NDIM];       // ping-pong h lo
__device__ float g_hfin[BATCH * NDIM];                    // final h fp32
__device__ unsigned g_gcnt[4 * 32];                       // init-barrier counters
__device__ unsigned g_ggen[4 * 32];                       // init-barrier generations
__device__ __align__(128) unsigned g_sflag[4][32];        // per-CTA step flags (1 line/group)

// ---------------------------------------------------------------------------
// Helpers
// ---------------------------------------------------------------------------
__device__ __forceinline__ uint32_t smem_u32(const void* p) {
    uint32_t a;
    asm("{ .reg .u64 t; cvta.to.shared.u64 t, %1; cvt.u32.u64 %0, t; }"
        : "=r"(a) : "l"(p));
    return a;
}

__device__ __forceinline__ void ldsm4(uint32_t (&r)[4], uint32_t addr) {
    asm volatile("ldmatrix.sync.aligned.m8n8.x4.shared.b16 {%0,%1,%2,%3}, [%4];"
                 : "=r"(r[0]), "=r"(r[1]), "=r"(r[2]), "=r"(r[3]) : "r"(addr));
}

__device__ __forceinline__ void mma_bf16(float (&d)[4], const uint32_t (&a)[4],
                                         const uint32_t b0, const uint32_t b1) {
    asm volatile(
        "mma.sync.aligned.m16n8k16.row.col.f32.bf16.bf16.f32 "
        "{%0,%1,%2,%3}, {%4,%5,%6,%7}, {%8,%9}, {%0,%1,%2,%3};"
        : "+f"(d[0]), "+f"(d[1]), "+f"(d[2]), "+f"(d[3])
        : "r"(a[0]), "r"(a[1]), "r"(a[2]), "r"(a[3]), "r"(b0), "r"(b1));
}

#define CP_ASYNC16(dst, src) \
    asm volatile("cp.async.cg.shared.global [%0], [%1], 16;" \
                 :: "r"(dst), "l"(src) : "memory")
#define CP_COMMIT() asm volatile("cp.async.commit_group;" ::: "memory")
#define CP_WAIT0()  asm volatile("cp.async.wait_group 0;" ::: "memory")
#define BAR_PAIR(id) asm volatile("bar.sync %0, 64;" :: "r"(id) : "memory")

// fast tanh: t = exp(-2|x|) in (0,1] (no overflow), r = sign(x)*(1-t)/(1+t)
__device__ __forceinline__ float tanh_fast(float x) {
    float t = __expf(-2.0f * fabsf(x));
    float r = 1.0f - __fdividef(2.0f * t, 1.0f + t);
    return copysignf(r, x);
}

// split 8 fp32 -> 8 bf16 hi + 8 bf16 lo (packed uint4 each)
__device__ __forceinline__ void split8(float4 f0, float4 f1, uint4& hi, uint4& lo) {
    float f[8] = {f0.x, f0.y, f0.z, f0.w, f1.x, f1.y, f1.z, f1.w};
    unsigned short h[8], l[8];
#pragma unroll
    for (int i = 0; i < 8; i++) {
        __nv_bfloat16 bh = __float2bfloat16_rn(f[i]);
        float r = f[i] - __bfloat162float(bh);
        h[i] = __bfloat16_as_ushort(bh);
        l[i] = __bfloat16_as_ushort(__float2bfloat16_rn(r));
    }
    hi.x = (uint32_t)h[0] | ((uint32_t)h[1] << 16);
    hi.y = (uint32_t)h[2] | ((uint32_t)h[3] << 16);
    hi.z = (uint32_t)h[4] | ((uint32_t)h[5] << 16);
    hi.w = (uint32_t)h[6] | ((uint32_t)h[7] << 16);
    lo.x = (uint32_t)l[0] | ((uint32_t)l[1] << 16);
    lo.y = (uint32_t)l[2] | ((uint32_t)l[3] << 16);
    lo.z = (uint32_t)l[4] | ((uint32_t)l[5] << 16);
    lo.w = (uint32_t)l[6] | ((uint32_t)l[7] << 16);
}

// split 2 fp32 -> packed bf16x2 hi + lo
__device__ __forceinline__ void split2(float a, float b, uint32_t& hi, uint32_t& lo) {
    __nv_bfloat16 ah = __float2bfloat16_rn(a), bh = __float2bfloat16_rn(b);
    float ar = a - __bfloat162float(ah), br = b - __bfloat162float(bh);
    hi = (uint32_t)__bfloat16_as_ushort(ah) |
         ((uint32_t)__bfloat16_as_ushort(bh) << 16);
    lo = (uint32_t)__bfloat16_as_ushort(__float2bfloat16_rn(ar)) |
         ((uint32_t)__bfloat16_as_ushort(__float2bfloat16_rn(br)) << 16);
}

// one-time 32-CTA group barrier (replay-safe, monotonic generation)
__device__ __forceinline__ void group_barrier(int grp) {
    __syncthreads();
    if (threadIdx.x == 0) {
        unsigned* cnt = &g_gcnt[grp * 32];
        volatile unsigned* gen = (volatile unsigned*)&g_ggen[grp * 32];
        unsigned myg = *gen;
        __threadfence();
        if (atomicAdd(cnt, 1) == 31) {
            atomicExch(cnt, 0);
            __threadfence();
            atomicAdd((unsigned*)gen, 1);
        } else {
            while (*gen == myg) { }
            __threadfence();
        }
    }
    __syncthreads();
}

// ---------------------------------------------------------------------------
// Setup kernels
// ---------------------------------------------------------------------------
__global__ void zero_hbf() {
    int idx = blockIdx.x * blockDim.x + threadIdx.x;
    if (idx < BATCH * NDIM) {
        g_hbf_hi[0][idx] = __float2bfloat16_rn(0.0f);
        g_hbf_lo[0][idx] = __float2bfloat16_rn(0.0f);
    }
}

// Transpose + split W [K,N] -> dst_hi/lo [N,K] bf16.  blockIdx.z: 0=W_xh, 1=W_hh
__global__ void wprep(const float* __restrict__ Wxh, const float* __restrict__ Whh) {
    __shared__ float t[32][33];
    const int which = blockIdx.z;
    const float* W = which ? Whh : Wxh;
    __nv_bfloat16* dhi = which ? g_Whh_hi : g_Wt_hi;
    __nv_bfloat16* dlo = which ? g_Whh_lo : g_Wt_lo;
    int tx = threadIdx.x, ty = threadIdx.y;
    int nb = blockIdx.x * 32, kb = blockIdx.y * 32;
#pragma unroll
    for (int i = ty; i < 32; i += 8)
        t[i][tx] = W[(size_t)(kb + i) * NDIM + nb + tx];
    __syncthreads();
#pragma unroll
    for (int i = ty; i < 32; i += 8) {
        float f = t[tx][i];
        __nv_bfloat16 bh = __float2bfloat16_rn(f);
        float r = f - __bfloat162float(bh);
        size_t off = (size_t)(nb + i) * NDIM + kb + tx;
        dhi[off] = bh;
        dlo[off] = __float2bfloat16_rn(r);
    }
}

// ---------------------------------------------------------------------------
// XP GEMM via mma.sync bf16-split (unchanged)
// ---------------------------------------------------------------------------
#define XP_ARR  10240
#define XP_BUF  (4 * XP_ARR)
#define XP_SMEM (2 * XP_BUF)

__global__ void __launch_bounds__(256) xp_gemm_mma(const float* __restrict__ A,
                                                   const float* __restrict__ bias) {
    extern __shared__ __align__(16) unsigned char sm[];
    const uint32_t sb = smem_u32(sm);
    const int tid = threadIdx.x, wid = tid >> 5, lane = tid & 31;
    const int cCol = blockIdx.x, cRow = blockIdx.y;
    const int wm = (wid >> 2) * 64;
    const int wn = (wid & 3) * 32;

    const int lrow = tid >> 1;
    const int lhf  = tid & 1;
    const float* Ag = A + (size_t)(cRow * 128 + lrow) * NDIM + lhf * 16;
    const __nv_bfloat16* Bhg = g_Wt_hi + (size_t)(cCol * 128 + lrow) * NDIM + lhf * 16;
    const __nv_bfloat16* Blg = g_Wt_lo + (size_t)(cCol * 128 + lrow) * NDIM + lhf * 16;
    unsigned char* st_a = sm + lrow * 80 + lhf * 32;
    unsigned char* st_b = sm + 2 * XP_ARR + lrow * 80 + lhf * 32;

    float acc[4][4][4];
#pragma unroll
    for (int i = 0; i < 4; i++)
#pragma unroll
        for (int j = 0; j < 4; j++)
#pragma unroll
            for (int q = 0; q < 4; q++) acc[i][j][q] = 0.0f;

    {
        float4 f0 = *(const float4*)(Ag + 0);
        float4 f1 = *(const float4*)(Ag + 4);
        float4 f2 = *(const float4*)(Ag + 8);
        float4 f3 = *(const float4*)(Ag + 12);
        uint4 h0, l0, h1, l1;
        split8(f0, f1, h0, l0);
        split8(f2, f3, h1, l1);
        *(uint4*)(st_a +  0) = h0; *(uint4*)(st_a + 16) = h1;
        *(uint4*)(st_a + XP_ARR +  0) = l0; *(uint4*)(st_a + XP_ARR + 16) = l1;
        uint4 bh0 = *(const uint4*)(Bhg);     uint4 bh1 = *(const uint4*)(Bhg + 8);
        uint4 bl0 = *(const uint4*)(Blg);     uint4 bl1 = *(const uint4*)(Blg + 8);
        *(uint4*)(st_b +  0) = bh0; *(uint4*)(st_b + 16) = bh1;
        *(uint4*)(st_b + XP_ARR +  0) = bl0; *(uint4*)(st_b + XP_ARR + 16) = bl1;
    }
    __syncthreads();

#pragma unroll 1
    for (int ko = 0; ko < 32; ko++) {
        const int buf = ko & 1;
        float4 f0, f1, f2, f3;
        uint4 pbh0, pbh1, pbl0, pbl1;
        if (ko < 31) {
            const float* Ap = Ag + (ko + 1) * 32;
            f0 = *(const float4*)(Ap + 0);  f1 = *(const float4*)(Ap + 4);
            f2 = *(const float4*)(Ap + 8);  f3 = *(const float4*)(Ap + 12);
            pbh0 = *(const uint4*)(Bhg + (ko + 1) * 32);
            pbh1 = *(const uint4*)(Bhg + (ko + 1) * 32 + 8);
            pbl0 = *(const uint4*)(Blg + (ko + 1) * 32);
            pbl1 = *(const uint4*)(Blg + (ko + 1) * 32 + 8);
        }

        const uint32_t base = sb + buf * XP_BUF;
#pragma unroll
        for (int s = 0; s < 2; s++) {
            const uint32_t k0b = s * 32;
            uint32_t ah[4][4], al[4][4];
#pragma unroll
            for (int mi = 0; mi < 4; mi++) {
                uint32_t ad = base + (wm + mi * 16 + (lane & 15)) * 80 + k0b + (lane >> 4) * 16;
                ldsm4(ah[mi], ad);
                ldsm4(al[mi], ad + XP_ARR);
            }
            uint32_t bh[4][2], bl[4][2];
#pragma unroll
            for (int nb = 0; nb < 2; nb++) {
                uint32_t bd = base + 2 * XP_ARR +
                              (wn + nb * 16 + (lane & 7) + ((lane >> 4) << 3)) * 80 +
                              k0b + (((lane >> 3) & 1) << 4);
                uint32_t r[4];
                ldsm4(r, bd);
                bh[nb * 2 + 0][0] = r[0]; bh[nb * 2 + 0][1] = r[1];
                bh[nb * 2 + 1][0] = r[2]; bh[nb * 2 + 1][1] = r[3];
                ldsm4(r, bd + XP_ARR);
                bl[nb * 2 + 0][0] = r[0]; bl[nb * 2 + 0][1] = r[1];
                bl[nb * 2 + 1][0] = r[2]; bl[nb * 2 + 1][1] = r[3];
            }
#pragma unroll
            for (int mi = 0; mi < 4; mi++)
#pragma unroll
                for (int nj = 0; nj < 4; nj++) {
                    mma_bf16(acc[mi][nj], ah[mi], bh[nj][0], bh[nj][1]);
                    mma_bf16(acc[mi][nj], ah[mi], bl[nj][0], bl[nj][1]);
                    mma_bf16(acc[mi][nj], al[mi], bh[nj][0], bh[nj][1]);
                }
        }

        if (ko < 31) {
            unsigned char* da = st_a + (buf ^ 1) * XP_BUF;
            unsigned char* db = st_b + (buf ^ 1) * XP_BUF;
            uint4 h0, l0, h1, l1;
            split8(f0, f1, h0, l0);
            split8(f2, f3, h1, l1);
            *(uint4*)(da +  0) = h0; *(uint4*)(da + 16) = h1;
            *(uint4*)(da + XP_ARR +  0) = l0; *(uint4*)(da + XP_ARR + 16) = l1;
            *(uint4*)(db +  0) = pbh0; *(uint4*)(db + 16) = pbh1;
            *(uint4*)(db + XP_ARR +  0) = pbl0; *(uint4*)(db + XP_ARR + 16) = pbl1;
            __syncthreads();
        }
    }

#pragma unroll
    for (int mi = 0; mi < 4; mi++) {
        int row = cRow * 128 + wm + mi * 16 + (lane >> 2);
#pragma unroll
        for (int nj = 0; nj < 4; nj++) {
            int col = cCol * 128 + wn + nj * 8 + (lane & 3) * 2;
            float b0 = bias[col], b1 = bias[col + 1];
            float2 v0 = {acc[mi][nj][0] + b0, acc[mi][nj][1] + b1};
            float2 v1 = {acc[mi][nj][2] + b0, acc[mi][nj][3] + b1};
            *(float2*)(g_xp + (size_t)row * NDIM + col) = v0;
            *(float2*)(g_xp + (size_t)(row + 8) * NDIM + col) = v1;
        }
    }
}

// ---------------------------------------------------------------------------
// Persistent recurrence v13: exact R15 structure + split-term accumulators.
// Each bf16-split term (AhBh / AhBl / AlBh) gets its own accumulator set so
// HMMA dependency chains per warp go from 2x48 to 6x16 — 3x the independent
// streams per SMSP. Terms are summed once in the epilogue (fp32, exact).
// ---------------------------------------------------------------------------
#define R4_WS     2064
#define R4_OFFW   0
#define R4_OFFWL  66048
#define R4_OFFH   132096
#define R4_PAIR   9216                 // per pair: 2 bufs x (hi 2304 + lo 2304)
#define R4_BUF    4608
#define R4_HLO    2304
#define R4_OFFRED (132096 + 8 * 9216)  // 205824
#define R4_REDSL  4096
#define R4_SMEM   (205824 + 3 * 4096)  // 218112

__global__ void __launch_bounds__(512) rnn_persistent13() {
    extern __shared__ __align__(16) unsigned char sm[];
    const uint32_t sb = smem_u32(sm);
    const int tid = threadIdx.x, wid = tid >> 5, lane = tid & 31;
    const int r  = blockIdx.x;
    const int mi = r >> 5;          // m-group 0..3
    const int nj = r & 31;          // n-block 0..31
    const int mq = (wid >> 1) & 1;  // quadrant m
    const int nq = wid & 1;         // quadrant n
    const int kq = wid >> 2;        // k-quarter 0..3
    const int pair = wid >> 1;      // 0..7 : (kq, mq) pair shared by nq=0,1
    const int barid = 1 + pair;     // named barrier ids 1..8 (15 = epilogue)

    // snapshot my lane's flag base BEFORE anyone publishes (replay-safe)
    const unsigned fbase = *((volatile unsigned*)&g_sflag[mi][lane]);
    const unsigned* fptr = &g_sflag[mi][lane];

    // ---- load W_hh^T rows [nj*32, +32) into smem (once, persistent) ----
    {
        const int n  = tid >> 4;             // 0..31
        const int sg = (tid & 15) * 128;     // byte offset within 2048B row
        const unsigned char* gh = (const unsigned char*)(g_Whh_hi + (size_t)(nj * 32 + n) * NDIM) + sg;
        const unsigned char* gl = (const unsigned char*)(g_Whh_lo + (size_t)(nj * 32 + n) * NDIM) + sg;
        uint32_t dh = sb + R4_OFFW  + n * R4_WS + sg;
        uint32_t dl = sb + R4_OFFWL + n * R4_WS + sg;
#pragma unroll
        for (int i = 0; i < 8; i++) {
            CP_ASYNC16(dh + i * 16, gh + i * 16);
            CP_ASYNC16(dl + i * 16, gl + i * 16);
        }
        CP_COMMIT();
    }

    group_barrier(mi);   // all snapshots taken; safe to start publishing

    // pair-local h loader geometry: 64 threads cover 16 rows x 128B
    const int ptid = nq * 32 + lane;        // 0..63 within pair
    const int prow = ptid >> 2;             // 0..15
    const int pseg = (ptid & 3) * 32;       // 0,32,64,96
    const uint32_t hpair = sb + R4_OFFH + pair * R4_PAIR;
    const uint32_t hdst  = hpair + prow * 144 + pseg;   // +buf*R4_BUF, lo +R4_HLO

    // epilogue geometry (kq==0 warps, wid 0..3)
    const int erow = mi * 32 + mq * 16 + (lane >> 2);
    const int ecol = nj * 32 + nq * 16 + (lane & 3) * 2;

    CP_WAIT0();
    __syncthreads();

    // ---- register-cache ks=0 W fragments (step-invariant) ----
    uint32_t wc_bh[4][4], wc_bl[4][4];
#pragma unroll
    for (int kk = 0; kk < 4; kk++) {
        uint32_t bd = sb + R4_OFFW +
                      (nq * 16 + (lane & 7) + ((lane >> 4) << 3)) * R4_WS +
                      (kq * 128 + kk * 32) + (((lane >> 3) & 1) << 4);
        ldsm4(wc_bh[kk], bd);
        ldsm4(wc_bl[kk], bd + (R4_OFFWL - R4_OFFW));
    }

#pragma unroll 1
    for (int t = 0; t < SEQ; t++) {
        // per-thread global h source: row mi*32+mq*16+prow, col window kq*128+pseg
        const unsigned char* HgH =
            (const unsigned char*)(g_hbf_hi[t & 1] + (size_t)(mi * 32 + mq * 16 + prow) * NDIM)
            + kq * 128 + pseg;
        const unsigned char* HgL =
            (const unsigned char*)(g_hbf_lo[t & 1] + (size_t)(mi * 32 + mq * 16 + prow) * NDIM)
            + kq * 128 + pseg;

        // xp prefetch (epilogue warps) — before any waiting
        float2 xp00, xp01, xp10, xp11;
        if (kq == 0) {
            const float* b0 = g_xp + ((size_t)erow * SEQ + t) * NDIM;
            const float* b1 = g_xp + ((size_t)(erow + 8) * SEQ + t) * NDIM;
            xp00 = *(const float2*)(b0 + ecol);
            xp01 = *(const float2*)(b0 + ecol + 8);
            xp10 = *(const float2*)(b1 + ecol);
            xp11 = *(const float2*)(b1 + ecol + 8);
        }

        // ---- wait: all 32 producers of h(t) published (acquire-load poll) ----
        if (t > 0) {
            const unsigned target = fbase + (unsigned)t;
            unsigned v;
            do {
                asm volatile("ld.global.acquire.gpu.b32 %0, [%1];"
                             : "=r"(v) : "l"(fptr) : "memory");
            } while (!__all_sync(0xFFFFFFFFu, (int)(v - target) >= 0));
        }

        // prologue: chunk 0 -> buf 0 (pair-local, 64-thread barrier)
        CP_ASYNC16(hdst,                HgH);
        CP_ASYNC16(hdst + 16,           HgH + 16);
        CP_ASYNC16(hdst + R4_HLO,       HgL);
        CP_ASYNC16(hdst + R4_HLO + 16,  HgL + 16);
        CP_COMMIT();
        CP_WAIT0();
        BAR_PAIR(barid);

        // split-term accumulators: independent HMMA chains
        float accA[2][4], accB[2][4], accC[2][4];
#pragma unroll
        for (int f = 0; f < 2; f++)
#pragma unroll
            for (int q = 0; q < 4; q++) {
                accA[f][q] = 0.0f; accB[f][q] = 0.0f; accC[f][q] = 0.0f;
            }

        // ---- ks = 0 (peeled: W from registers) ----
        {
            const uint32_t d2 = hdst + R4_BUF;
            CP_ASYNC16(d2,               HgH + 512);
            CP_ASYNC16(d2 + 16,          HgH + 512 + 16);
            CP_ASYNC16(d2 + R4_HLO,      HgL + 512);
            CP_ASYNC16(d2 + R4_HLO + 16, HgL + 512 + 16);
            CP_COMMIT();

#pragma unroll
            for (int kk = 0; kk < 4; kk++) {
                uint32_t ah[4], al[4];
                uint32_t ad = hpair + (lane & 15) * 144 + kk * 32 + (lane >> 4) * 16;
                ldsm4(ah, ad);
                ldsm4(al, ad + R4_HLO);
#pragma unroll
                for (int f = 0; f < 2; f++) {
                    mma_bf16(accA[f], ah, wc_bh[kk][f * 2], wc_bh[kk][f * 2 + 1]);
                    mma_bf16(accB[f], ah, wc_bl[kk][f * 2], wc_bl[kk][f * 2 + 1]);
                    mma_bf16(accC[f], al, wc_bh[kk][f * 2], wc_bh[kk][f * 2 + 1]);
                }
            }
            CP_WAIT0();
            BAR_PAIR(barid);
        }

        // ---- ks = 1..3 (W via ldsm) ----
#pragma unroll 1
        for (int ks = 1; ks < 4; ks++) {
            const int buf = ks & 1;

            if (ks < 3) {
                const uint32_t d2 = hdst + (buf ^ 1) * R4_BUF;
                CP_ASYNC16(d2,               HgH + (ks + 1) * 512);
                CP_ASYNC16(d2 + 16,          HgH + (ks + 1) * 512 + 16);
                CP_ASYNC16(d2 + R4_HLO,      HgL + (ks + 1) * 512);
                CP_ASYNC16(d2 + R4_HLO + 16, HgL + (ks + 1) * 512 + 16);
                CP_COMMIT();
            }

            const uint32_t abase = hpair + buf * R4_BUF;
#pragma unroll
            for (int kk = 0; kk < 4; kk++) {
                const uint32_t gkb = ks * 512 + kq * 128 + kk * 32;   // W byte offset
                uint32_t ah[4], al[4];
                uint32_t ad = abase + (lane & 15) * 144 + kk * 32 + (lane >> 4) * 16;
                ldsm4(ah, ad);
                ldsm4(al, ad + R4_HLO);

                uint32_t bh[4], bl[4];
                uint32_t bd = sb + R4_OFFW +
                              (nq * 16 + (lane & 7) + ((lane >> 4) << 3)) * R4_WS +
                              gkb + (((lane >> 3) & 1) << 4);
                ldsm4(bh, bd);
                ldsm4(bl, bd + (R4_OFFWL - R4_OFFW));

#pragma unroll
                for (int f = 0; f < 2; f++) {
                    mma_bf16(accA[f], ah, bh[f * 2], bh[f * 2 + 1]);
                    mma_bf16(accB[f], ah, bl[f * 2], bl[f * 2 + 1]);
                    mma_bf16(accC[f], al, bh[f * 2], bh[f * 2 + 1]);
                }
            }

            if (ks < 3) {
                CP_WAIT0();
                BAR_PAIR(barid);
            }
        }

        // sum split terms (exact fp32 adds)
        float acc[2][4];
#pragma unroll
        for (int f = 0; f < 2; f++)
#pragma unroll
            for (int q = 0; q < 4; q++)
                acc[f][q] = accA[f][q] + accB[f][q] + accC[f][q];

        // ---- combine 4 k-quarters via smem (block-wide, 1 syncthreads) ----
        if (kq > 0) {
            unsigned char* red = sm + R4_OFFRED + (kq - 1) * R4_REDSL +
                                 (((mq * 2 + nq) * 32 + lane) * 32);
            *(float4*)(red +  0) = make_float4(acc[0][0], acc[0][1], acc[0][2], acc[0][3]);
            *(float4*)(red + 16) = make_float4(acc[1][0], acc[1][1], acc[1][2], acc[1][3]);
        }
        __syncthreads();

        if (kq == 0) {
#pragma unroll
            for (int s = 0; s < 3; s++) {
                const unsigned char* red = sm + R4_OFFRED + s * R4_REDSL +
                                           (((mq * 2 + nq) * 32 + lane) * 32);
                float4 r0 = *(const float4*)(red +  0);
                float4 r1 = *(const float4*)(red + 16);
                acc[0][0] += r0.x; acc[0][1] += r0.y; acc[0][2] += r0.z; acc[0][3] += r0.w;
                acc[1][0] += r1.x; acc[1][1] += r1.y; acc[1][2] += r1.z; acc[1][3] += r1.w;
            }

            __nv_bfloat16* WH = g_hbf_hi[(t + 1) & 1];
            __nv_bfloat16* WL = g_hbf_lo[(t + 1) & 1];

            float a00 = tanh_fast(acc[0][0] + xp00.x), a01 = tanh_fast(acc[0][1] + xp00.y);
            float a80 = tanh_fast(acc[1][0] + xp01.x), a81 = tanh_fast(acc[1][1] + xp01.y);
            float b00 = tanh_fast(acc[0][2] + xp10.x), b01 = tanh_fast(acc[0][3] + xp10.y);
            float b80 = tanh_fast(acc[1][2] + xp11.x), b81 = tanh_fast(acc[1][3] + xp11.y);

            uint32_t ph, pl;
            size_t o00 = (size_t)erow * NDIM + ecol;
            size_t o01 = o00 + 8;
            size_t o10 = (size_t)(erow + 8) * NDIM + ecol;
            size_t o11 = o10 + 8;
            split2(a00, a01, ph, pl); *(uint32_t*)&WH[o00] = ph; *(uint32_t*)&WL[o00] = pl;
            split2(a80, a81, ph, pl); *(uint32_t*)&WH[o01] = ph; *(uint32_t*)&WL[o01] = pl;
            split2(b00, b01, ph, pl); *(uint32_t*)&WH[o10] = ph; *(uint32_t*)&WL[o10] = pl;
            split2(b80, b81, ph, pl); *(uint32_t*)&WH[o11] = ph; *(uint32_t*)&WL[o11] = pl;

            // publish h(t+1): only the 4 epilogue warps need to converge.
            asm volatile("bar.sync 15, 128;" ::: "memory");
            if (tid == 0) {
                __threadfence();
                atomicAdd(&g_sflag[mi][nj], 1u);
            }

            if (t == SEQ - 1) {
                *(float2*)(g_hfin + o00) = make_float2(a00, a01);
                *(float2*)(g_hfin + o01) = make_float2(a80, a81);
                *(float2*)(g_hfin + o10) = make_float2(b00, b01);
                *(float2*)(g_hfin + o11) = make_float2(b80, b81);
            }
        }
        // warps 4..15: no final full-CTA barrier — next step's flag wait
        // (which includes own CTA's flag) transitively orders everything.
    }
}

// ---------------------------------------------------------------------------
// Final: out = h_final @ W_hy + b_y
// ---------------------------------------------------------------------------
__global__ void __launch_bounds__(128) rnn_final(const float* __restrict__ W,
                                                 const float* __restrict__ bias,
                                                 float* __restrict__ out) {
    __shared__ float As[32 * 34];
    __shared__ float Bs[32 * 32];

    const float* __restrict__ H = g_hfin;

    const int tid = threadIdx.x;
    const int bx  = blockIdx.x;
    const int by  = blockIdx.y;

    const int rI = tid / 8;
    const int cI = (tid % 8) * 4;
    const int tr = tid / 8;
    const int tc = tid % 8;

    float acc[2][4];
#pragma unroll
    for (int i = 0; i < 2; i++)
#pragma unroll
        for (int q = 0; q < 4; q++) acc[i][q] = 0.0f;

    for (int bk = 0; bk < NDIM; bk += 32) {
#pragma unroll
        for (int rr = 0; rr < 2; rr++) {
            int rw = rI + rr * 16;
            float4 a = *(const float4*)(H + (by * 32 + rw) * NDIM + bk + cI);
            As[(cI + 0) * 34 + rw] = a.x;
            As[(cI + 1) * 34 + rw] = a.y;
            As[(cI + 2) * 34 + rw] = a.z;
            As[(cI + 3) * 34 + rw] = a.w;
            *(float4*)(Bs + rw * 32 + cI) =
                *(const float4*)(W + (size_t)(bk + rw) * NDIM + bx * 32 + cI);
        }
        __syncthreads();

#pragma unroll
        for (int k = 0; k < 32; k++) {
            float2 av = *(const float2*)(As + k * 34 + tr * 2);
            float4 bv = *(const float4*)(Bs + k * 32 + tc * 4);
            acc[0][0] += av.x * bv.x; acc[0][1] += av.x * bv.y;
            acc[0][2] += av.x * bv.z; acc[0][3] += av.x * bv.w;
            acc[1][0] += av.y * bv.x; acc[1][1] += av.y * bv.y;
            acc[1][2] += av.y * bv.z; acc[1][3] += av.y * bv.w;
        }
        __syncthreads();
    }

    const int col = bx * 32 + tc * 4;
    float4 bv4 = *(const float4*)(bias + col);
#pragma unroll
    for (int i = 0; i < 2; i++) {
        int row = by * 32 + tr * 2 + i;
        float4 v;
        v.x = acc[i][0] + bv4.x;
        v.y = acc[i][1] + bv4.y;
        v.z = acc[i][2] + bv4.z;
        v.w = acc[i][3] + bv4.w;
        *(float4*)(out + row * NDIM + col) = v;
    }
}

// ---------------------------------------------------------------------------
// kernel_launch — graph-capturable
// ---------------------------------------------------------------------------
extern "C" void kernel_launch(void* const* d_in, const int* in_sizes, int n_in,
                              void* d_out, int out_size) {
    (void)in_sizes; (void)n_in; (void)out_size;
    const float* x    = (const float*)d_in[0];
    const float* W_xh = (const float*)d_in[1];
    const float* W_hh = (const float*)d_in[2];
    const float* b_h  = (const float*)d_in[3];
    const float* W_hy = (const float*)d_in[4];
    const float* b_y  = (const float*)d_in[5];
    float* out = (float*)d_out;

    cudaFuncSetAttribute(xp_gemm_mma, cudaFuncAttributeMaxDynamicSharedMemorySize, XP_SMEM);
    cudaFuncSetAttribute(rnn_persistent13, cudaFuncAttributeMaxDynamicSharedMemorySize, R4_SMEM);

    zero_hbf<<<(BATCH * NDIM + 511) / 512, 512>>>();

    dim3 gridW(NDIM / 32, NDIM / 32, 2);            // both weight preps in one launch
    wprep<<<gridW, dim3(32, 8)>>>(W_xh, W_hh);

    dim3 gridXP(NDIM / 128, (BATCH * SEQ) / 128);   // (8, 512)
    xp_gemm_mma<<<gridXP, 256, XP_SMEM>>>(x, b_h);

    rnn_persistent13<<<RGRID, 512, R4_SMEM>>>();

    dim3 gridFin(NDIM / 32, BATCH / 32);
    rnn_final<<<gridFin, 128>>>(W_hy, b_y, out);
}

// round 17
// speedup vs baseline: 1.1118x; 1.0828x over previous
#include <cuda_runtime.h>
#include <cuda_bf16.h>
#include <math.h>
#include <stdint.h>

#define BATCH 128
#define SEQ   512
#define NDIM  1024
#define RGRID 128          // persistent CTAs: 4 m-groups x 32 n-blocks

// ---------------------------------------------------------------------------
// Global scratch (allocation-free)
// ---------------------------------------------------------------------------
__device__ float g_xp[(size_t)BATCH * SEQ * NDIM];        // 256 MB
__device__ __nv_bfloat16 g_Wt_hi[(size_t)NDIM * NDIM];    // W_xh^T hi  [N][K]
__device__ __nv_bfloat16 g_Wt_lo[(size_t)NDIM * NDIM];
__device__ __nv_bfloat16 g_Whh_hi[(size_t)NDIM * NDIM];   // W_hh^T hi  [N][K]
__device__ __nv_bfloat16 g_Whh_lo[(size_t)NDIM * NDIM];
__device__ __nv_bfloat16 g_hbf_hi[2][BATCH * NDIM];       // ping-pong h hi
__device__ __nv_bfloat16 g_hbf_lo[2][BATCH * NDIM];       // ping-pong h lo
__device__ float g_hfin[BATCH * NDIM];                    // final h fp32
__device__ unsigned g_gcnt[4 * 32];                       // init-barrier counters
__device__ unsigned g_ggen[4 * 32];                       // init-barrier generations
__device__ __align__(128) unsigned g_sflag[4][32];        // per-CTA step flags (1 line/group)

// ---------------------------------------------------------------------------
// Helpers
// ---------------------------------------------------------------------------
__device__ __forceinline__ uint32_t smem_u32(const void* p) {
    uint32_t a;
    asm("{ .reg .u64 t; cvta.to.shared.u64 t, %1; cvt.u32.u64 %0, t; }"
        : "=r"(a) : "l"(p));
    return a;
}

__device__ __forceinline__ void ldsm4(uint32_t (&r)[4], uint32_t addr) {
    asm volatile("ldmatrix.sync.aligned.m8n8.x4.shared.b16 {%0,%1,%2,%3}, [%4];"
                 : "=r"(r[0]), "=r"(r[1]), "=r"(r[2]), "=r"(r[3]) : "r"(addr));
}

__device__ __forceinline__ void mma_bf16(float (&d)[4], const uint32_t (&a)[4],
                                         const uint32_t b0, const uint32_t b1) {
    asm volatile(
        "mma.sync.aligned.m16n8k16.row.col.f32.bf16.bf16.f32 "
        "{%0,%1,%2,%3}, {%4,%5,%6,%7}, {%8,%9}, {%0,%1,%2,%3};"
        : "+f"(d[0]), "+f"(d[1]), "+f"(d[2]), "+f"(d[3])
        : "r"(a[0]), "r"(a[1]), "r"(a[2]), "r"(a[3]), "r"(b0), "r"(b1));
}

#define CP_ASYNC16(dst, src) \
    asm volatile("cp.async.cg.shared.global [%0], [%1], 16;" \
                 :: "r"(dst), "l"(src) : "memory")
#define CP_COMMIT() asm volatile("cp.async.commit_group;" ::: "memory")
#define CP_WAIT0()  asm volatile("cp.async.wait_group 0;" ::: "memory")
#define BAR_PAIR(id) asm volatile("bar.sync %0, 64;" :: "r"(id) : "memory")

// fast tanh: t = exp(-2|x|) in (0,1] (no overflow), r = sign(x)*(1-t)/(1+t)
__device__ __forceinline__ float tanh_fast(float x) {
    float t = __expf(-2.0f * fabsf(x));
    float r = 1.0f - __fdividef(2.0f * t, 1.0f + t);
    return copysignf(r, x);
}

// split 8 fp32 -> 8 bf16 hi + 8 bf16 lo (packed uint4 each)
__device__ __forceinline__ void split8(float4 f0, float4 f1, uint4& hi, uint4& lo) {
    float f[8] = {f0.x, f0.y, f0.z, f0.w, f1.x, f1.y, f1.z, f1.w};
    unsigned short h[8], l[8];
#pragma unroll
    for (int i = 0; i < 8; i++) {
        __nv_bfloat16 bh = __float2bfloat16_rn(f[i]);
        float r = f[i] - __bfloat162float(bh);
        h[i] = __bfloat16_as_ushort(bh);
        l[i] = __bfloat16_as_ushort(__float2bfloat16_rn(r));
    }
    hi.x = (uint32_t)h[0] | ((uint32_t)h[1] << 16);
    hi.y = (uint32_t)h[2] | ((uint32_t)h[3] << 16);
    hi.z = (uint32_t)h[4] | ((uint32_t)h[5] << 16);
    hi.w = (uint32_t)h[6] | ((uint32_t)h[7] << 16);
    lo.x = (uint32_t)l[0] | ((uint32_t)l[1] << 16);
    lo.y = (uint32_t)l[2] | ((uint32_t)l[3] << 16);
    lo.z = (uint32_t)l[4] | ((uint32_t)l[5] << 16);
    lo.w = (uint32_t)l[6] | ((uint32_t)l[7] << 16);
}

// split 2 fp32 -> packed bf16x2 hi + lo
__device__ __forceinline__ void split2(float a, float b, uint32_t& hi, uint32_t& lo) {
    __nv_bfloat16 ah = __float2bfloat16_rn(a), bh = __float2bfloat16_rn(b);
    float ar = a - __bfloat162float(ah), br = b - __bfloat162float(bh);
    hi = (uint32_t)__bfloat16_as_ushort(ah) |
         ((uint32_t)__bfloat16_as_ushort(bh) << 16);
    lo = (uint32_t)__bfloat16_as_ushort(__float2bfloat16_rn(ar)) |
         ((uint32_t)__bfloat16_as_ushort(__float2bfloat16_rn(br)) << 16);
}

// one-time 32-CTA group barrier (replay-safe, monotonic generation)
__device__ __forceinline__ void group_barrier(int grp) {
    __syncthreads();
    if (threadIdx.x == 0) {
        unsigned* cnt = &g_gcnt[grp * 32];
        volatile unsigned* gen = (volatile unsigned*)&g_ggen[grp * 32];
        unsigned myg = *gen;
        __threadfence();
        if (atomicAdd(cnt, 1) == 31) {
            atomicExch(cnt, 0);
            __threadfence();
            atomicAdd((unsigned*)gen, 1);
        } else {
            while (*gen == myg) { }
            __threadfence();
        }
    }
    __syncthreads();
}

// ---------------------------------------------------------------------------
// Setup kernels
// ---------------------------------------------------------------------------
__global__ void zero_hbf() {
    int idx = blockIdx.x * blockDim.x + threadIdx.x;
    if (idx < BATCH * NDIM) {
        g_hbf_hi[0][idx] = __float2bfloat16_rn(0.0f);
        g_hbf_lo[0][idx] = __float2bfloat16_rn(0.0f);
    }
}

// Transpose + split W [K,N] -> dst_hi/lo [N,K] bf16.  blockIdx.z: 0=W_xh, 1=W_hh
__global__ void wprep(const float* __restrict__ Wxh, const float* __restrict__ Whh) {
    __shared__ float t[32][33];
    const int which = blockIdx.z;
    const float* W = which ? Whh : Wxh;
    __nv_bfloat16* dhi = which ? g_Whh_hi : g_Wt_hi;
    __nv_bfloat16* dlo = which ? g_Whh_lo : g_Wt_lo;
    int tx = threadIdx.x, ty = threadIdx.y;
    int nb = blockIdx.x * 32, kb = blockIdx.y * 32;
#pragma unroll
    for (int i = ty; i < 32; i += 8)
        t[i][tx] = W[(size_t)(kb + i) * NDIM + nb + tx];
    __syncthreads();
#pragma unroll
    for (int i = ty; i < 32; i += 8) {
        float f = t[tx][i];
        __nv_bfloat16 bh = __float2bfloat16_rn(f);
        float r = f - __bfloat162float(bh);
        size_t off = (size_t)(nb + i) * NDIM + kb + tx;
        dhi[off] = bh;
        dlo[off] = __float2bfloat16_rn(r);
    }
}

// ---------------------------------------------------------------------------
// XP GEMM via mma.sync bf16-split.
// NEW: __launch_bounds__(256, 2) caps regs at 128 so 2 CTAs co-reside per SM
// (2 x 80 KB smem = 160 KB < 228 KB) — doubles latency hiding across the
// per-ko syncthreads and ldsm->HMMA chains.
// ---------------------------------------------------------------------------
#define XP_ARR  10240
#define XP_BUF  (4 * XP_ARR)
#define XP_SMEM (2 * XP_BUF)

__global__ void __launch_bounds__(256, 2) xp_gemm_mma(const float* __restrict__ A,
                                                      const float* __restrict__ bias) {
    extern __shared__ __align__(16) unsigned char sm[];
    const uint32_t sb = smem_u32(sm);
    const int tid = threadIdx.x, wid = tid >> 5, lane = tid & 31;
    const int cCol = blockIdx.x, cRow = blockIdx.y;
    const int wm = (wid >> 2) * 64;
    const int wn = (wid & 3) * 32;

    const int lrow = tid >> 1;
    const int lhf  = tid & 1;
    const float* Ag = A + (size_t)(cRow * 128 + lrow) * NDIM + lhf * 16;
    const __nv_bfloat16* Bhg = g_Wt_hi + (size_t)(cCol * 128 + lrow) * NDIM + lhf * 16;
    const __nv_bfloat16* Blg = g_Wt_lo + (size_t)(cCol * 128 + lrow) * NDIM + lhf * 16;
    unsigned char* st_a = sm + lrow * 80 + lhf * 32;
    unsigned char* st_b = sm + 2 * XP_ARR + lrow * 80 + lhf * 32;

    float acc[4][4][4];
#pragma unroll
    for (int i = 0; i < 4; i++)
#pragma unroll
        for (int j = 0; j < 4; j++)
#pragma unroll
            for (int q = 0; q < 4; q++) acc[i][j][q] = 0.0f;

    {
        float4 f0 = *(const float4*)(Ag + 0);
        float4 f1 = *(const float4*)(Ag + 4);
        float4 f2 = *(const float4*)(Ag + 8);
        float4 f3 = *(const float4*)(Ag + 12);
        uint4 h0, l0, h1, l1;
        split8(f0, f1, h0, l0);
        split8(f2, f3, h1, l1);
        *(uint4*)(st_a +  0) = h0; *(uint4*)(st_a + 16) = h1;
        *(uint4*)(st_a + XP_ARR +  0) = l0; *(uint4*)(st_a + XP_ARR + 16) = l1;
        uint4 bh0 = *(const uint4*)(Bhg);     uint4 bh1 = *(const uint4*)(Bhg + 8);
        uint4 bl0 = *(const uint4*)(Blg);     uint4 bl1 = *(const uint4*)(Blg + 8);
        *(uint4*)(st_b +  0) = bh0; *(uint4*)(st_b + 16) = bh1;
        *(uint4*)(st_b + XP_ARR +  0) = bl0; *(uint4*)(st_b + XP_ARR + 16) = bl1;
    }
    __syncthreads();

#pragma unroll 1
    for (int ko = 0; ko < 32; ko++) {
        const int buf = ko & 1;
        float4 f0, f1, f2, f3;
        uint4 pbh0, pbh1, pbl0, pbl1;
        if (ko < 31) {
            const float* Ap = Ag + (ko + 1) * 32;
            f0 = *(const float4*)(Ap + 0);  f1 = *(const float4*)(Ap + 4);
            f2 = *(const float4*)(Ap + 8);  f3 = *(const float4*)(Ap + 12);
            pbh0 = *(const uint4*)(Bhg + (ko + 1) * 32);
            pbh1 = *(const uint4*)(Bhg + (ko + 1) * 32 + 8);
            pbl0 = *(const uint4*)(Blg + (ko + 1) * 32);
            pbl1 = *(const uint4*)(Blg + (ko + 1) * 32 + 8);
        }

        const uint32_t base = sb + buf * XP_BUF;
#pragma unroll
        for (int s = 0; s < 2; s++) {
            const uint32_t k0b = s * 32;
            uint32_t ah[4][4], al[4][4];
#pragma unroll
            for (int mi = 0; mi < 4; mi++) {
                uint32_t ad = base + (wm + mi * 16 + (lane & 15)) * 80 + k0b + (lane >> 4) * 16;
                ldsm4(ah[mi], ad);
                ldsm4(al[mi], ad + XP_ARR);
            }
            uint32_t bh[4][2], bl[4][2];
#pragma unroll
            for (int nb = 0; nb < 2; nb++) {
                uint32_t bd = base + 2 * XP_ARR +
                              (wn + nb * 16 + (lane & 7) + ((lane >> 4) << 3)) * 80 +
                              k0b + (((lane >> 3) & 1) << 4);
                uint32_t r[4];
                ldsm4(r, bd);
                bh[nb * 2 + 0][0] = r[0]; bh[nb * 2 + 0][1] = r[1];
                bh[nb * 2 + 1][0] = r[2]; bh[nb * 2 + 1][1] = r[3];
                ldsm4(r, bd + XP_ARR);
                bl[nb * 2 + 0][0] = r[0]; bl[nb * 2 + 0][1] = r[1];
                bl[nb * 2 + 1][0] = r[2]; bl[nb * 2 + 1][1] = r[3];
            }
#pragma unroll
            for (int mi = 0; mi < 4; mi++)
#pragma unroll
                for (int nj = 0; nj < 4; nj++) {
                    mma_bf16(acc[mi][nj], ah[mi], bh[nj][0], bh[nj][1]);
                    mma_bf16(acc[mi][nj], ah[mi], bl[nj][0], bl[nj][1]);
                    mma_bf16(acc[mi][nj], al[mi], bh[nj][0], bh[nj][1]);
                }
        }

        if (ko < 31) {
            unsigned char* da = st_a + (buf ^ 1) * XP_BUF;
            unsigned char* db = st_b + (buf ^ 1) * XP_BUF;
            uint4 h0, l0, h1, l1;
            split8(f0, f1, h0, l0);
            split8(f2, f3, h1, l1);
            *(uint4*)(da +  0) = h0; *(uint4*)(da + 16) = h1;
            *(uint4*)(da + XP_ARR +  0) = l0; *(uint4*)(da + XP_ARR + 16) = l1;
            *(uint4*)(db +  0) = pbh0; *(uint4*)(db + 16) = pbh1;
            *(uint4*)(db + XP_ARR +  0) = pbl0; *(uint4*)(db + XP_ARR + 16) = pbl1;
            __syncthreads();
        }
    }

#pragma unroll
    for (int mi = 0; mi < 4; mi++) {
        int row = cRow * 128 + wm + mi * 16 + (lane >> 2);
#pragma unroll
        for (int nj = 0; nj < 4; nj++) {
            int col = cCol * 128 + wn + nj * 8 + (lane & 3) * 2;
            float b0 = bias[col], b1 = bias[col + 1];
            float2 v0 = {acc[mi][nj][0] + b0, acc[mi][nj][1] + b1};
            float2 v1 = {acc[mi][nj][2] + b0, acc[mi][nj][3] + b1};
            *(float2*)(g_xp + (size_t)row * NDIM + col) = v0;
            *(float2*)(g_xp + (size_t)(row + 8) * NDIM + col) = v1;
        }
    }
}

// ---------------------------------------------------------------------------
// Persistent recurrence v13 (R16 winner, unchanged): per-pair h staging,
// ks=0 W register cache, split-term accumulators, fast tanh, flag sync.
// ---------------------------------------------------------------------------
#define R4_WS     2064
#define R4_OFFW   0
#define R4_OFFWL  66048
#define R4_OFFH   132096
#define R4_PAIR   9216                 // per pair: 2 bufs x (hi 2304 + lo 2304)
#define R4_BUF    4608
#define R4_HLO    2304
#define R4_OFFRED (132096 + 8 * 9216)  // 205824
#define R4_REDSL  4096
#define R4_SMEM   (205824 + 3 * 4096)  // 218112

__global__ void __launch_bounds__(512) rnn_persistent13() {
    extern __shared__ __align__(16) unsigned char sm[];
    const uint32_t sb = smem_u32(sm);
    const int tid = threadIdx.x, wid = tid >> 5, lane = tid & 31;
    const int r  = blockIdx.x;
    const int mi = r >> 5;          // m-group 0..3
    const int nj = r & 31;          // n-block 0..31
    const int mq = (wid >> 1) & 1;  // quadrant m
    const int nq = wid & 1;         // quadrant n
    const int kq = wid >> 2;        // k-quarter 0..3
    const int pair = wid >> 1;      // 0..7 : (kq, mq) pair shared by nq=0,1
    const int barid = 1 + pair;     // named barrier ids 1..8 (15 = epilogue)

    // snapshot my lane's flag base BEFORE anyone publishes (replay-safe)
    const unsigned fbase = *((volatile unsigned*)&g_sflag[mi][lane]);
    const unsigned* fptr = &g_sflag[mi][lane];

    // ---- load W_hh^T rows [nj*32, +32) into smem (once, persistent) ----
    {
        const int n  = tid >> 4;             // 0..31
        const int sg = (tid & 15) * 128;     // byte offset within 2048B row
        const unsigned char* gh = (const unsigned char*)(g_Whh_hi + (size_t)(nj * 32 + n) * NDIM) + sg;
        const unsigned char* gl = (const unsigned char*)(g_Whh_lo + (size_t)(nj * 32 + n) * NDIM) + sg;
        uint32_t dh = sb + R4_OFFW  + n * R4_WS + sg;
        uint32_t dl = sb + R4_OFFWL + n * R4_WS + sg;
#pragma unroll
        for (int i = 0; i < 8; i++) {
            CP_ASYNC16(dh + i * 16, gh + i * 16);
            CP_ASYNC16(dl + i * 16, gl + i * 16);
        }
        CP_COMMIT();
    }

    group_barrier(mi);   // all snapshots taken; safe to start publishing

    // pair-local h loader geometry: 64 threads cover 16 rows x 128B
    const int ptid = nq * 32 + lane;        // 0..63 within pair
    const int prow = ptid >> 2;             // 0..15
    const int pseg = (ptid & 3) * 32;       // 0,32,64,96
    const uint32_t hpair = sb + R4_OFFH + pair * R4_PAIR;
    const uint32_t hdst  = hpair + prow * 144 + pseg;   // +buf*R4_BUF, lo +R4_HLO

    // epilogue geometry (kq==0 warps, wid 0..3)
    const int erow = mi * 32 + mq * 16 + (lane >> 2);
    const int ecol = nj * 32 + nq * 16 + (lane & 3) * 2;

    CP_WAIT0();
    __syncthreads();

    // ---- register-cache ks=0 W fragments (step-invariant) ----
    uint32_t wc_bh[4][4], wc_bl[4][4];
#pragma unroll
    for (int kk = 0; kk < 4; kk++) {
        uint32_t bd = sb + R4_OFFW +
                      (nq * 16 + (lane & 7) + ((lane >> 4) << 3)) * R4_WS +
                      (kq * 128 + kk * 32) + (((lane >> 3) & 1) << 4);
        ldsm4(wc_bh[kk], bd);
        ldsm4(wc_bl[kk], bd + (R4_OFFWL - R4_OFFW));
    }

#pragma unroll 1
    for (int t = 0; t < SEQ; t++) {
        // per-thread global h source: row mi*32+mq*16+prow, col window kq*128+pseg
        const unsigned char* HgH =
            (const unsigned char*)(g_hbf_hi[t & 1] + (size_t)(mi * 32 + mq * 16 + prow) * NDIM)
            + kq * 128 + pseg;
        const unsigned char* HgL =
            (const unsigned char*)(g_hbf_lo[t & 1] + (size_t)(mi * 32 + mq * 16 + prow) * NDIM)
            + kq * 128 + pseg;

        // xp prefetch (epilogue warps) — before any waiting
        float2 xp00, xp01, xp10, xp11;
        if (kq == 0) {
            const float* b0 = g_xp + ((size_t)erow * SEQ + t) * NDIM;
            const float* b1 = g_xp + ((size_t)(erow + 8) * SEQ + t) * NDIM;
            xp00 = *(const float2*)(b0 + ecol);
            xp01 = *(const float2*)(b0 + ecol + 8);
            xp10 = *(const float2*)(b1 + ecol);
            xp11 = *(const float2*)(b1 + ecol + 8);
        }

        // ---- wait: all 32 producers of h(t) published (acquire-load poll) ----
        if (t > 0) {
            const unsigned target = fbase + (unsigned)t;
            unsigned v;
            do {
                asm volatile("ld.global.acquire.gpu.b32 %0, [%1];"
                             : "=r"(v) : "l"(fptr) : "memory");
            } while (!__all_sync(0xFFFFFFFFu, (int)(v - target) >= 0));
        }

        // prologue: chunk 0 -> buf 0 (pair-local, 64-thread barrier)
        CP_ASYNC16(hdst,                HgH);
        CP_ASYNC16(hdst + 16,           HgH + 16);
        CP_ASYNC16(hdst + R4_HLO,       HgL);
        CP_ASYNC16(hdst + R4_HLO + 16,  HgL + 16);
        CP_COMMIT();
        CP_WAIT0();
        BAR_PAIR(barid);

        // split-term accumulators: independent HMMA chains
        float accA[2][4], accB[2][4], accC[2][4];
#pragma unroll
        for (int f = 0; f < 2; f++)
#pragma unroll
            for (int q = 0; q < 4; q++) {
                accA[f][q] = 0.0f; accB[f][q] = 0.0f; accC[f][q] = 0.0f;
            }

        // ---- ks = 0 (peeled: W from registers) ----
        {
            const uint32_t d2 = hdst + R4_BUF;
            CP_ASYNC16(d2,               HgH + 512);
            CP_ASYNC16(d2 + 16,          HgH + 512 + 16);
            CP_ASYNC16(d2 + R4_HLO,      HgL + 512);
            CP_ASYNC16(d2 + R4_HLO + 16, HgL + 512 + 16);
            CP_COMMIT();

#pragma unroll
            for (int kk = 0; kk < 4; kk++) {
                uint32_t ah[4], al[4];
                uint32_t ad = hpair + (lane & 15) * 144 + kk * 32 + (lane >> 4) * 16;
                ldsm4(ah, ad);
                ldsm4(al, ad + R4_HLO);
#pragma unroll
                for (int f = 0; f < 2; f++) {
                    mma_bf16(accA[f], ah, wc_bh[kk][f * 2], wc_bh[kk][f * 2 + 1]);
                    mma_bf16(accB[f], ah, wc_bl[kk][f * 2], wc_bl[kk][f * 2 + 1]);
                    mma_bf16(accC[f], al, wc_bh[kk][f * 2], wc_bh[kk][f * 2 + 1]);
                }
            }
            CP_WAIT0();
            BAR_PAIR(barid);
        }

        // ---- ks = 1..3 (W via ldsm) ----
#pragma unroll 1
        for (int ks = 1; ks < 4; ks++) {
            const int buf = ks & 1;

            if (ks < 3) {
                const uint32_t d2 = hdst + (buf ^ 1) * R4_BUF;
                CP_ASYNC16(d2,               HgH + (ks + 1) * 512);
                CP_ASYNC16(d2 + 16,          HgH + (ks + 1) * 512 + 16);
                CP_ASYNC16(d2 + R4_HLO,      HgL + (ks + 1) * 512);
                CP_ASYNC16(d2 + R4_HLO + 16, HgL + (ks + 1) * 512 + 16);
                CP_COMMIT();
            }

            const uint32_t abase = hpair + buf * R4_BUF;
#pragma unroll
            for (int kk = 0; kk < 4; kk++) {
                const uint32_t gkb = ks * 512 + kq * 128 + kk * 32;   // W byte offset
                uint32_t ah[4], al[4];
                uint32_t ad = abase + (lane & 15) * 144 + kk * 32 + (lane >> 4) * 16;
                ldsm4(ah, ad);
                ldsm4(al, ad + R4_HLO);

                uint32_t bh[4], bl[4];
                uint32_t bd = sb + R4_OFFW +
                              (nq * 16 + (lane & 7) + ((lane >> 4) << 3)) * R4_WS +
                              gkb + (((lane >> 3) & 1) << 4);
                ldsm4(bh, bd);
                ldsm4(bl, bd + (R4_OFFWL - R4_OFFW));

#pragma unroll
                for (int f = 0; f < 2; f++) {
                    mma_bf16(accA[f], ah, bh[f * 2], bh[f * 2 + 1]);
                    mma_bf16(accB[f], ah, bl[f * 2], bl[f * 2 + 1]);
                    mma_bf16(accC[f], al, bh[f * 2], bh[f * 2 + 1]);
                }
            }

            if (ks < 3) {
                CP_WAIT0();
                BAR_PAIR(barid);
            }
        }

        // sum split terms (exact fp32 adds)
        float acc[2][4];
#pragma unroll
        for (int f = 0; f < 2; f++)
#pragma unroll
            for (int q = 0; q < 4; q++)
                acc[f][q] = accA[f][q] + accB[f][q] + accC[f][q];

        // ---- combine 4 k-quarters via smem (block-wide, 1 syncthreads) ----
        if (kq > 0) {
            unsigned char* red = sm + R4_OFFRED + (kq - 1) * R4_REDSL +
                                 (((mq * 2 + nq) * 32 + lane) * 32);
            *(float4*)(red +  0) = make_float4(acc[0][0], acc[0][1], acc[0][2], acc[0][3]);
            *(float4*)(red + 16) = make_float4(acc[1][0], acc[1][1], acc[1][2], acc[1][3]);
        }
        __syncthreads();

        if (kq == 0) {
#pragma unroll
            for (int s = 0; s < 3; s++) {
                const unsigned char* red = sm + R4_OFFRED + s * R4_REDSL +
                                           (((mq * 2 + nq) * 32 + lane) * 32);
                float4 r0 = *(const float4*)(red +  0);
                float4 r1 = *(const float4*)(red + 16);
                acc[0][0] += r0.x; acc[0][1] += r0.y; acc[0][2] += r0.z; acc[0][3] += r0.w;
                acc[1][0] += r1.x; acc[1][1] += r1.y; acc[1][2] += r1.z; acc[1][3] += r1.w;
            }

            __nv_bfloat16* WH = g_hbf_hi[(t + 1) & 1];
            __nv_bfloat16* WL = g_hbf_lo[(t + 1) & 1];

            float a00 = tanh_fast(acc[0][0] + xp00.x), a01 = tanh_fast(acc[0][1] + xp00.y);
            float a80 = tanh_fast(acc[1][0] + xp01.x), a81 = tanh_fast(acc[1][1] + xp01.y);
            float b00 = tanh_fast(acc[0][2] + xp10.x), b01 = tanh_fast(acc[0][3] + xp10.y);
            float b80 = tanh_fast(acc[1][2] + xp11.x), b81 = tanh_fast(acc[1][3] + xp11.y);

            uint32_t ph, pl;
            size_t o00 = (size_t)erow * NDIM + ecol;
            size_t o01 = o00 + 8;
            size_t o10 = (size_t)(erow + 8) * NDIM + ecol;
            size_t o11 = o10 + 8;
            split2(a00, a01, ph, pl); *(uint32_t*)&WH[o00] = ph; *(uint32_t*)&WL[o00] = pl;
            split2(a80, a81, ph, pl); *(uint32_t*)&WH[o01] = ph; *(uint32_t*)&WL[o01] = pl;
            split2(b00, b01, ph, pl); *(uint32_t*)&WH[o10] = ph; *(uint32_t*)&WL[o10] = pl;
            split2(b80, b81, ph, pl); *(uint32_t*)&WH[o11] = ph; *(uint32_t*)&WL[o11] = pl;

            // publish h(t+1): only the 4 epilogue warps need to converge.
            asm volatile("bar.sync 15, 128;" ::: "memory");
            if (tid == 0) {
                __threadfence();
                atomicAdd(&g_sflag[mi][nj], 1u);
            }

            if (t == SEQ - 1) {
                *(float2*)(g_hfin + o00) = make_float2(a00, a01);
                *(float2*)(g_hfin + o01) = make_float2(a80, a81);
                *(float2*)(g_hfin + o10) = make_float2(b00, b01);
                *(float2*)(g_hfin + o11) = make_float2(b80, b81);
            }
        }
        // warps 4..15: no final full-CTA barrier — next step's flag wait
        // (which includes own CTA's flag) transitively orders everything.
    }
}

// ---------------------------------------------------------------------------
// Final: out = h_final @ W_hy + b_y
// ---------------------------------------------------------------------------
__global__ void __launch_bounds__(128) rnn_final(const float* __restrict__ W,
                                                 const float* __restrict__ bias,
                                                 float* __restrict__ out) {
    __shared__ float As[32 * 34];
    __shared__ float Bs[32 * 32];

    const float* __restrict__ H = g_hfin;

    const int tid = threadIdx.x;
    const int bx  = blockIdx.x;
    const int by  = blockIdx.y;

    const int rI = tid / 8;
    const int cI = (tid % 8) * 4;
    const int tr = tid / 8;
    const int tc = tid % 8;

    float acc[2][4];
#pragma unroll
    for (int i = 0; i < 2; i++)
#pragma unroll
        for (int q = 0; q < 4; q++) acc[i][q] = 0.0f;

    for (int bk = 0; bk < NDIM; bk += 32) {
#pragma unroll
        for (int rr = 0; rr < 2; rr++) {
            int rw = rI + rr * 16;
            float4 a = *(const float4*)(H + (by * 32 + rw) * NDIM + bk + cI);
            As[(cI + 0) * 34 + rw] = a.x;
            As[(cI + 1) * 34 + rw] = a.y;
            As[(cI + 2) * 34 + rw] = a.z;
            As[(cI + 3) * 34 + rw] = a.w;
            *(float4*)(Bs + rw * 32 + cI) =
                *(const float4*)(W + (size_t)(bk + rw) * NDIM + bx * 32 + cI);
        }
        __syncthreads();

#pragma unroll
        for (int k = 0; k < 32; k++) {
            float2 av = *(const float2*)(As + k * 34 + tr * 2);
            float4 bv = *(const float4*)(Bs + k * 32 + tc * 4);
            acc[0][0] += av.x * bv.x; acc[0][1] += av.x * bv.y;
            acc[0][2] += av.x * bv.z; acc[0][3] += av.x * bv.w;
            acc[1][0] += av.y * bv.x; acc[1][1] += av.y * bv.y;
            acc[1][2] += av.y * bv.z; acc[1][3] += av.y * bv.w;
        }
        __syncthreads();
    }

    const int col = bx * 32 + tc * 4;
    float4 bv4 = *(const float4*)(bias + col);
#pragma unroll
    for (int i = 0; i < 2; i++) {
        int row = by * 32 + tr * 2 + i;
        float4 v;
        v.x = acc[i][0] + bv4.x;
        v.y = acc[i][1] + bv4.y;
        v.z = acc[i][2] + bv4.z;
        v.w = acc[i][3] + bv4.w;
        *(float4*)(out + row * NDIM + col) = v;
    }
}

// ---------------------------------------------------------------------------
// kernel_launch — graph-capturable
// ---------------------------------------------------------------------------
extern "C" void kernel_launch(void* const* d_in, const int* in_sizes, int n_in,
                              void* d_out, int out_size) {
    (void)in_sizes; (void)n_in; (void)out_size;
    const float* x    = (const float*)d_in[0];
    const float* W_xh = (const float*)d_in[1];
    const float* W_hh = (const float*)d_in[2];
    const float* b_h  = (const float*)d_in[3];
    const float* W_hy = (const float*)d_in[4];
    const float* b_y  = (const float*)d_in[5];
    float* out = (float*)d_out;

    cudaFuncSetAttribute(xp_gemm_mma, cudaFuncAttributeMaxDynamicSharedMemorySize, XP_SMEM);
    cudaFuncSetAttribute(rnn_persistent13, cudaFuncAttributeMaxDynamicSharedMemorySize, R4_SMEM);

    zero_hbf<<<(BATCH * NDIM + 511) / 512, 512>>>();

    dim3 gridW(NDIM / 32, NDIM / 32, 2);            // both weight preps in one launch
    wprep<<<gridW, dim3(32, 8)>>>(W_xh, W_hh);

    dim3 gridXP(NDIM / 128, (BATCH * SEQ) / 128);   // (8, 512)
    xp_gemm_mma<<<gridXP, 256, XP_SMEM>>>(x, b_h);

    rnn_persistent13<<<RGRID, 512, R4_SMEM>>>();

    dim3 gridFin(NDIM / 32, BATCH / 32);
    rnn_final<<<gridFin, 128>>>(W_hy, b_y, out);
}